// round 14
// baseline (speedup 1.0000x reference)
#include <cuda_runtime.h>
#include <cuda_fp16.h>
#include <stdint.h>
#include <math.h>

#define T_ 1024
#define S_ 1024
#define B_ 4
#define D_ 512
#define H_ 8
#define HD_ 64
#define DFF_ 2048
#define W_ 16
#define NROWS (T_ * B_)
#define SCALE_ 0.125f
#define LOG2E_ 1.4426950408889634f
#define EPS_ 1e-5f

// fp32 region (float offsets)
#define FOFF_X1     0
#define FOFF_X2     2097152
#define FOFF_BCAT   4194304
#define HALF_BASE_F 5000000

// half region (half offsets)
#define HOFF_QKV    0
#define HOFF_ATTN   6291456
#define HOFF_SWQ    8388608
#define HOFF_SWKV   10485760
#define HOFF_SWATTN 14680064
#define HOFF_HBUF   16777216
#define HOFF_TGT    25165824
#define HOFF_MEM    27262976
#define HOFF_X1H    29360128
#define HOFF_X2H    31457280
#define HOFF_WIN    33554432
#define HOFF_WOUT   34340864
#define HOFF_WSWQ   34603008
#define HOFF_WSWKV  34865152
#define HOFF_WSWO   35389440
#define HOFF_WLIN1  35651584
#define HOFF_WLIN2  36700160
#define HOFF_PROJ16 37748736
#define HOFF_FF16   39845888

#define SCRATCH_FLOATS 33554432
__device__ float g_scratch[SCRATCH_FLOATS];

// ---------------------------------------------------------------------------
// PTX helpers
// ---------------------------------------------------------------------------
__device__ __forceinline__ void cp_async16(void* smem_ptr, const void* gmem_ptr) {
    unsigned saddr = (unsigned)__cvta_generic_to_shared(smem_ptr);
    asm volatile("cp.async.cg.shared.global [%0], [%1], 16;\n"
                 :: "r"(saddr), "l"(gmem_ptr));
}
__device__ __forceinline__ void cp_commit() {
    asm volatile("cp.async.commit_group;\n");
}
__device__ __forceinline__ void cp_wait0() {
    asm volatile("cp.async.wait_group 0;\n");
}
__device__ __forceinline__ void cp_wait1() {
    asm volatile("cp.async.wait_group 1;\n");
}
__device__ __forceinline__ void ldsm_x4h(unsigned& r0, unsigned& r1, unsigned& r2, unsigned& r3,
                                         const __half* p) {
    unsigned saddr = (unsigned)__cvta_generic_to_shared((void*)p);
    asm volatile("ldmatrix.sync.aligned.m8n8.x4.shared.b16 {%0,%1,%2,%3}, [%4];\n"
                 : "=r"(r0), "=r"(r1), "=r"(r2), "=r"(r3) : "r"(saddr));
}
__device__ __forceinline__ void ldsm_x4h_t(unsigned& r0, unsigned& r1, unsigned& r2, unsigned& r3,
                                           const __half* p) {
    unsigned saddr = (unsigned)__cvta_generic_to_shared((void*)p);
    asm volatile("ldmatrix.sync.aligned.m8n8.x4.trans.shared.b16 {%0,%1,%2,%3}, [%4];\n"
                 : "=r"(r0), "=r"(r1), "=r"(r2), "=r"(r3) : "r"(saddr));
}
__device__ __forceinline__ void mma_f16(float& c0, float& c1, float& c2, float& c3,
                                        unsigned a0, unsigned a1, unsigned a2, unsigned a3,
                                        unsigned b0, unsigned b1) {
    asm volatile("mma.sync.aligned.m16n8k16.row.col.f32.f16.f16.f32 "
                 "{%0,%1,%2,%3}, {%4,%5,%6,%7}, {%8,%9}, {%0,%1,%2,%3};\n"
                 : "+f"(c0), "+f"(c1), "+f"(c2), "+f"(c3)
                 : "r"(a0), "r"(a1), "r"(a2), "r"(a3), "r"(b0), "r"(b1));
}

// ---------------------------------------------------------------------------
// fp32->fp16 fused convert: 10 segments incl. KV weight concat + bias copy.
// ---------------------------------------------------------------------------
__global__ void __launch_bounds__(256) f2h_multi_kernel(
    const float* __restrict__ s0, __half* __restrict__ d0,
    const float* __restrict__ s1, __half* __restrict__ d1,
    const float* __restrict__ s2, __half* __restrict__ d2,
    const float* __restrict__ s3, __half* __restrict__ d3,
    const float* __restrict__ s4, __half* __restrict__ d4,
    const float* __restrict__ s5, __half* __restrict__ d5,
    const float* __restrict__ s6, __half* __restrict__ d6,
    const float* __restrict__ s7, __half* __restrict__ d7,
    const float* __restrict__ s8, __half* __restrict__ d8,
    const float* __restrict__ s9, __half* __restrict__ d9,
    const float* __restrict__ kb, const float* __restrict__ vb,
    float* __restrict__ bcat)
{
    if (blockIdx.x == 0) {
        int t = threadIdx.x;
        bcat[t] = kb[t];          bcat[512 + t] = vb[t];
        bcat[256 + t] = kb[256 + t]; bcat[768 + t] = vb[256 + t];
    }
    int idx = (blockIdx.x * 256 + threadIdx.x) * 4;
    const float* src; __half* dst; int off;
    if      (idx < 2097152) { src = s0; dst = d0; off = idx; }
    else if (idx < 4194304) { src = s1; dst = d1; off = idx - 2097152; }
    else if (idx < 4980736) { src = s2; dst = d2; off = idx - 4194304; }
    else if (idx < 5242880) { src = s3; dst = d3; off = idx - 4980736; }
    else if (idx < 5505024) { src = s4; dst = d4; off = idx - 5242880; }
    else if (idx < 5767168) { src = s5; dst = d5; off = idx - 5505024; }
    else if (idx < 6815744) { src = s6; dst = d6; off = idx - 5767168; }
    else if (idx < 7864320) { src = s7; dst = d7; off = idx - 6815744; }
    else if (idx < 8126464) { src = s8; dst = d8; off = idx - 7864320; }
    else                    { src = s9; dst = d9; off = idx - 8126464; }
    float4 v = *reinterpret_cast<const float4*>(src + off);
    *reinterpret_cast<__half2*>(dst + off)     = __floats2half2_rn(v.x, v.y);
    *reinterpret_cast<__half2*>(dst + off + 2) = __floats2half2_rn(v.z, v.w);
}

// ---------------------------------------------------------------------------
// FP16 GEMM 128x128 core (device function), BK=64, 3-stage pipeline.
// ---------------------------------------------------------------------------
#define STR64 72
#define ASTG (128 * STR64)
#define G128_SMEM (6 * ASTG * 2)

__device__ __forceinline__ void gemm128_body(
    const __half* __restrict__ A, const __half* __restrict__ Wt,
    const float* __restrict__ bias, void* __restrict__ Cout,
    int N, int K, int relu, int out16, int m0, int n0, __half* sg)
{
    __half* As = sg;
    __half* Bs = sg + 3 * ASTG;

    const int tid  = threadIdx.x;
    const int wid  = tid >> 5;
    const int lane = tid & 31;
    const int wm   = (wid & 3) * 32;
    const int wn   = (wid >> 2) * 64;

    float acc[2][8][4];
#pragma unroll
    for (int i = 0; i < 2; ++i)
#pragma unroll
        for (int j = 0; j < 8; ++j)
#pragma unroll
            for (int q = 0; q < 4; ++q) acc[i][j][q] = 0.f;

    const int ntiles = K / 64;
    const __half* Abase = A + (size_t)m0 * K;
    const __half* Bbase = Wt + (size_t)n0 * K;

    auto load_stage = [&](int t, int st) {
        int k0 = t * 64;
        __half* Ad = As + st * ASTG;
        __half* Bd = Bs + st * ASTG;
#pragma unroll
        for (int it = 0; it < 4; ++it) {
            int idx = it * 256 + tid;
            int row = idx >> 3, col = (idx & 7) * 8;
            cp_async16(&Ad[row * STR64 + col], Abase + (size_t)row * K + k0 + col);
            cp_async16(&Bd[row * STR64 + col], Bbase + (size_t)row * K + k0 + col);
        }
    };

    load_stage(0, 0); cp_commit();
    load_stage(1, 1); cp_commit();

    const int a_row = wm + (lane & 15);
    const int a_koff = (lane >> 4) * 8;
    const int b_row_base = wn + (lane & 7) + ((lane >> 4) * 8);
    const int b_koff = ((lane >> 3) & 1) * 8;

    for (int t = 0; t < ntiles; ++t) {
        cp_wait1();
        __syncthreads();

        int ps = t + 2;
        if (ps < ntiles) load_stage(ps, ps % 3);
        cp_commit();

        const int buf = t % 3;
        const __half* Ab = As + buf * ASTG;
        const __half* Bb = Bs + buf * ASTG;
#pragma unroll
        for (int ks = 0; ks < 4; ++ks) {
            unsigned a[2][4];
            unsigned b[8][2];
#pragma unroll
            for (int im = 0; im < 2; ++im)
                ldsm_x4h(a[im][0], a[im][1], a[im][2], a[im][3],
                         &Ab[(a_row + im * 16) * STR64 + ks * 16 + a_koff]);
#pragma unroll
            for (int ng = 0; ng < 4; ++ng) {
                unsigned r0, r1, r2, r3;
                ldsm_x4h(r0, r1, r2, r3,
                         &Bb[(b_row_base + ng * 16) * STR64 + ks * 16 + b_koff]);
                b[ng * 2][0] = r0; b[ng * 2][1] = r1;
                b[ng * 2 + 1][0] = r2; b[ng * 2 + 1][1] = r3;
            }
#pragma unroll
            for (int im = 0; im < 2; ++im)
#pragma unroll
                for (int in = 0; in < 8; ++in)
                    mma_f16(acc[im][in][0], acc[im][in][1], acc[im][in][2], acc[im][in][3],
                            a[im][0], a[im][1], a[im][2], a[im][3],
                            b[in][0], b[in][1]);
        }
    }

    const int row_base = m0 + wm + (lane >> 2);
    const int col_base = n0 + wn + (lane & 3) * 2;
#pragma unroll
    for (int im = 0; im < 2; ++im) {
#pragma unroll
        for (int in = 0; in < 8; ++in) {
            int col = col_base + in * 8;
            float b0 = bias[col], b1 = bias[col + 1];
            int r0 = row_base + im * 16;
            float v0 = acc[im][in][0] + b0;
            float v1 = acc[im][in][1] + b1;
            float v2 = acc[im][in][2] + b0;
            float v3 = acc[im][in][3] + b1;
            if (relu) {
                v0 = fmaxf(v0, 0.f); v1 = fmaxf(v1, 0.f);
                v2 = fmaxf(v2, 0.f); v3 = fmaxf(v3, 0.f);
            }
            if (out16) {
                __half* C = (__half*)Cout;
                *reinterpret_cast<__half2*>(&C[(size_t)r0 * N + col]) = __floats2half2_rn(v0, v1);
                *reinterpret_cast<__half2*>(&C[(size_t)(r0 + 8) * N + col]) = __floats2half2_rn(v2, v3);
            } else {
                float* C = (float*)Cout;
                C[(size_t)r0 * N + col] = v0;
                C[(size_t)r0 * N + col + 1] = v1;
                C[(size_t)(r0 + 8) * N + col] = v2;
                C[(size_t)(r0 + 8) * N + col + 1] = v3;
            }
        }
    }
}

__global__ void __launch_bounds__(256, 2) gemm_f16_kernel(
    const __half* __restrict__ A, const __half* __restrict__ Wt,
    const float* __restrict__ bias, void* __restrict__ Cout,
    int M, int N, int K, int relu, int out16)
{
    extern __shared__ __half sg[];
    gemm128_body(A, Wt, bias, Cout, N, K, relu, out16,
                 blockIdx.y * 128, blockIdx.x * 128, sg);
}

// Dual-problem GEMM: blockIdx.x < split -> problem 1, else problem 2.
__global__ void __launch_bounds__(256, 2) gemm_f16_dual_kernel(
    const __half* __restrict__ A1, const __half* __restrict__ W1,
    const float* __restrict__ b1, void* __restrict__ C1, int N1,
    const __half* __restrict__ A2, const __half* __restrict__ W2,
    const float* __restrict__ b2, void* __restrict__ C2, int N2,
    int K, int split)
{
    extern __shared__ __half sg[];
    if ((int)blockIdx.x < split)
        gemm128_body(A1, W1, b1, C1, N1, K, 0, 1,
                     blockIdx.y * 128, blockIdx.x * 128, sg);
    else
        gemm128_body(A2, W2, b2, C2, N2, K, 0, 1,
                     blockIdx.y * 128, (blockIdx.x - split) * 128, sg);
}

// ---------------------------------------------------------------------------
// FP16 GEMM 128x64, BK=64, 3-stage.
// ---------------------------------------------------------------------------
#define BSTG64 (64 * STR64)
#define G64_SMEM ((3 * ASTG + 3 * BSTG64) * 2)

__global__ void __launch_bounds__(256, 2) gemm_f16_n64_kernel(
    const __half* __restrict__ A, const __half* __restrict__ Wt,
    const float* __restrict__ bias, void* __restrict__ Cout,
    int M, int N, int K, int relu, int out16)
{
    extern __shared__ __half sg[];
    __half* As = sg;
    __half* Bs = sg + 3 * ASTG;

    const int tid  = threadIdx.x;
    const int wid  = tid >> 5;
    const int lane = tid & 31;
    const int wm   = (wid & 3) * 32;
    const int wn   = (wid >> 2) * 32;
    const int m0   = blockIdx.y * 128;
    const int n0   = blockIdx.x * 64;

    float acc[2][4][4];
#pragma unroll
    for (int i = 0; i < 2; ++i)
#pragma unroll
        for (int j = 0; j < 4; ++j)
#pragma unroll
            for (int q = 0; q < 4; ++q) acc[i][j][q] = 0.f;

    const int ntiles = K / 64;
    const __half* Abase = A + (size_t)m0 * K;
    const __half* Bbase = Wt + (size_t)n0 * K;

    auto load_stage = [&](int t, int st) {
        int k0 = t * 64;
        __half* Ad = As + st * ASTG;
        __half* Bd = Bs + st * BSTG64;
#pragma unroll
        for (int it = 0; it < 4; ++it) {
            int idx = it * 256 + tid;
            int row = idx >> 3, col = (idx & 7) * 8;
            cp_async16(&Ad[row * STR64 + col], Abase + (size_t)row * K + k0 + col);
        }
#pragma unroll
        for (int it = 0; it < 2; ++it) {
            int idx = it * 256 + tid;
            int row = idx >> 3, col = (idx & 7) * 8;
            cp_async16(&Bd[row * STR64 + col], Bbase + (size_t)row * K + k0 + col);
        }
    };

    load_stage(0, 0); cp_commit();
    load_stage(1, 1); cp_commit();

    const int a_row = wm + (lane & 15);
    const int a_koff = (lane >> 4) * 8;
    const int b_row_base = wn + (lane & 7) + ((lane >> 4) * 8);
    const int b_koff = ((lane >> 3) & 1) * 8;

    for (int t = 0; t < ntiles; ++t) {
        cp_wait1();
        __syncthreads();

        int ps = t + 2;
        if (ps < ntiles) load_stage(ps, ps % 3);
        cp_commit();

        const int buf = t % 3;
        const __half* Ab = As + buf * ASTG;
        const __half* Bb = Bs + buf * BSTG64;
#pragma unroll
        for (int ks = 0; ks < 4; ++ks) {
            unsigned a[2][4];
            unsigned b[4][2];
#pragma unroll
            for (int im = 0; im < 2; ++im)
                ldsm_x4h(a[im][0], a[im][1], a[im][2], a[im][3],
                         &Ab[(a_row + im * 16) * STR64 + ks * 16 + a_koff]);
#pragma unroll
            for (int ng = 0; ng < 2; ++ng) {
                unsigned r0, r1, r2, r3;
                ldsm_x4h(r0, r1, r2, r3,
                         &Bb[(b_row_base + ng * 16) * STR64 + ks * 16 + b_koff]);
                b[ng * 2][0] = r0; b[ng * 2][1] = r1;
                b[ng * 2 + 1][0] = r2; b[ng * 2 + 1][1] = r3;
            }
#pragma unroll
            for (int im = 0; im < 2; ++im)
#pragma unroll
                for (int in = 0; in < 4; ++in)
                    mma_f16(acc[im][in][0], acc[im][in][1], acc[im][in][2], acc[im][in][3],
                            a[im][0], a[im][1], a[im][2], a[im][3],
                            b[in][0], b[in][1]);
        }
    }

    const int row_base = m0 + wm + (lane >> 2);
    const int col_base = n0 + wn + (lane & 3) * 2;
#pragma unroll
    for (int im = 0; im < 2; ++im) {
#pragma unroll
        for (int in = 0; in < 4; ++in) {
            int col = col_base + in * 8;
            float b0 = bias[col], b1 = bias[col + 1];
            int r0 = row_base + im * 16;
            float v0 = acc[im][in][0] + b0;
            float v1 = acc[im][in][1] + b1;
            float v2 = acc[im][in][2] + b0;
            float v3 = acc[im][in][3] + b1;
            if (relu) {
                v0 = fmaxf(v0, 0.f); v1 = fmaxf(v1, 0.f);
                v2 = fmaxf(v2, 0.f); v3 = fmaxf(v3, 0.f);
            }
            if (out16) {
                __half* C = (__half*)Cout;
                *reinterpret_cast<__half2*>(&C[(size_t)r0 * N + col]) = __floats2half2_rn(v0, v1);
                *reinterpret_cast<__half2*>(&C[(size_t)(r0 + 8) * N + col]) = __floats2half2_rn(v2, v3);
            } else {
                float* C = (float*)Cout;
                C[(size_t)r0 * N + col] = v0;
                C[(size_t)r0 * N + col + 1] = v1;
                C[(size_t)(r0 + 8) * N + col] = v2;
                C[(size_t)(r0 + 8) * N + col + 1] = v3;
            }
        }
    }
}

// ---------------------------------------------------------------------------
// FP16 flash self-attention: 128-key tiles (softmax per 64-key half),
// register P, exp2-domain softmax.
// smem halfs: Ps[128*72] | Ks[2][128*72] | Vs[2][128*72]  (92160 B)
// ---------------------------------------------------------------------------
#define ASTRH 72
#define KB128 (128 * ASTRH)
#define ROWH 6144
#define ATTN_SMEM ((128 + 4 * 128) * ASTRH * 2)

__global__ void __launch_bounds__(256, 2) self_attn_f16_kernel(
    const __half* __restrict__ qkv, __half* __restrict__ out)
{
    extern __shared__ __half smh[];
    __half* Ps = smh;
    __half* Ks = smh + 128 * ASTRH;
    __half* Vs = Ks + 2 * KB128;

    const int tid = threadIdx.x;
    const int wid = tid >> 5;
    const int lane = tid & 31;
    const int b = blockIdx.y >> 3;
    const int h = blockIdx.y & 7;
    const int t0 = blockIdx.x * 128;
    const int wm = wid * 16;

    const __half* qbase = qkv + ((size_t)t0 * B_ + b) * 1536 + h * 64;
    const __half* kroot = qkv + (size_t)b * 1536 + 512 + h * 64;
    const __half* vroot = qkv + (size_t)b * 1536 + 1024 + h * 64;

#pragma unroll
    for (int i = 0; i < 4; ++i) {
        int idx = i * 256 + tid;
        int r = idx >> 3, c = (idx & 7) * 8;
        cp_async16(&Ps[r * ASTRH + c], qbase + (size_t)r * ROWH + c);
    }
    // K/V tile 0 (keys 0..127)
#pragma unroll
    for (int i = 0; i < 4; ++i) {
        int idx = i * 256 + tid;
        int r = idx >> 3, c = (idx & 7) * 8;
        cp_async16(&Ks[r * ASTRH + c], kroot + (size_t)r * ROWH + c);
        cp_async16(&Vs[r * ASTRH + c], vroot + (size_t)r * ROWH + c);
    }
    cp_commit();
    cp_wait0();
    __syncthreads();

    unsigned qf[4][4];
    {
        const __half2 sc2 = __float2half2_rn(SCALE_ * LOG2E_);
        const int qrow = wm + (lane & 15);
        const int qko = (lane >> 4) * 8;
#pragma unroll
        for (int ks = 0; ks < 4; ++ks) {
            unsigned r0, r1, r2, r3;
            ldsm_x4h(r0, r1, r2, r3, &Ps[qrow * ASTRH + ks * 16 + qko]);
            unsigned rr[4] = {r0, r1, r2, r3};
#pragma unroll
            for (int j = 0; j < 4; ++j) {
                __half2 v = *reinterpret_cast<__half2*>(&rr[j]);
                v = __hmul2(v, sc2);
                qf[ks][j] = *reinterpret_cast<unsigned*>(&v);
            }
        }
    }

    float o[8][4];
#pragma unroll
    for (int n = 0; n < 8; ++n)
#pragma unroll
        for (int c = 0; c < 4; ++c) o[n][c] = 0.f;
    float m0 = -1e30f, m1 = -1e30f, l0 = 0.f, l1 = 0.f;

    const int brow_base = (lane & 7) + ((lane >> 4) * 8);
    const int bko = ((lane >> 3) & 1) * 8;
    const int prow0 = wm + (lane >> 2);
    const int pcol = 2 * (lane & 3);
    const int v_row = lane & 15;
    const int v_coff = (lane >> 4) * 8;

    for (int kt = 0; kt < 8; ++kt) {
        const int buf = kt & 1;

        if (kt + 1 < 8) {
            const __half* kb = kroot + (size_t)(kt + 1) * 128 * ROWH;
            const __half* vb = vroot + (size_t)(kt + 1) * 128 * ROWH;
            __half* kd = Ks + (buf ^ 1) * KB128;
            __half* vd = Vs + (buf ^ 1) * KB128;
#pragma unroll
            for (int i = 0; i < 4; ++i) {
                int idx = i * 256 + tid;
                int r = idx >> 3, c = (idx & 7) * 8;
                cp_async16(&kd[r * ASTRH + c], kb + (size_t)r * ROWH + c);
                cp_async16(&vd[r * ASTRH + c], vb + (size_t)r * ROWH + c);
            }
            cp_commit();
            cp_wait1();
        } else {
            cp_wait0();
        }
        __syncthreads();

#pragma unroll
        for (int half = 0; half < 2; ++half) {
            const __half* Kb = Ks + buf * KB128 + half * 64 * ASTRH;
            const __half* Vb = Vs + buf * KB128 + half * 64 * ASTRH;

            float s[8][4];
#pragma unroll
            for (int n = 0; n < 8; ++n)
#pragma unroll
                for (int c = 0; c < 4; ++c) s[n][c] = 0.f;
#pragma unroll
            for (int ks = 0; ks < 4; ++ks) {
#pragma unroll
                for (int ng = 0; ng < 4; ++ng) {
                    unsigned r0, r1, r2, r3;
                    ldsm_x4h(r0, r1, r2, r3, &Kb[(brow_base + ng * 16) * ASTRH + ks * 16 + bko]);
                    mma_f16(s[ng * 2][0], s[ng * 2][1], s[ng * 2][2], s[ng * 2][3],
                            qf[ks][0], qf[ks][1], qf[ks][2], qf[ks][3], r0, r1);
                    mma_f16(s[ng * 2 + 1][0], s[ng * 2 + 1][1], s[ng * 2 + 1][2], s[ng * 2 + 1][3],
                            qf[ks][0], qf[ks][1], qf[ks][2], qf[ks][3], r2, r3);
                }
            }

            float mx0 = -1e30f, mx1 = -1e30f;
#pragma unroll
            for (int n = 0; n < 8; ++n) {
                mx0 = fmaxf(mx0, fmaxf(s[n][0], s[n][1]));
                mx1 = fmaxf(mx1, fmaxf(s[n][2], s[n][3]));
            }
            mx0 = fmaxf(mx0, __shfl_xor_sync(0xffffffffu, mx0, 1));
            mx0 = fmaxf(mx0, __shfl_xor_sync(0xffffffffu, mx0, 2));
            mx1 = fmaxf(mx1, __shfl_xor_sync(0xffffffffu, mx1, 1));
            mx1 = fmaxf(mx1, __shfl_xor_sync(0xffffffffu, mx1, 2));

            float mn0 = fmaxf(m0, mx0), mn1 = fmaxf(m1, mx1);
            float corr0 = exp2f(m0 - mn0), corr1 = exp2f(m1 - mn1);
            m0 = mn0; m1 = mn1;
            l0 *= corr0; l1 *= corr1;
#pragma unroll
            for (int n = 0; n < 8; ++n) {
                o[n][0] *= corr0; o[n][1] *= corr0;
                o[n][2] *= corr1; o[n][3] *= corr1;
            }

            unsigned pf[4][4];
#pragma unroll
            for (int j = 0; j < 4; ++j) {
                float p00 = exp2f(s[2 * j][0] - mn0);
                float p01 = exp2f(s[2 * j][1] - mn0);
                float p02 = exp2f(s[2 * j][2] - mn1);
                float p03 = exp2f(s[2 * j][3] - mn1);
                float p10 = exp2f(s[2 * j + 1][0] - mn0);
                float p11 = exp2f(s[2 * j + 1][1] - mn0);
                float p12 = exp2f(s[2 * j + 1][2] - mn1);
                float p13 = exp2f(s[2 * j + 1][3] - mn1);
                l0 += p00 + p01 + p10 + p11;
                l1 += p02 + p03 + p12 + p13;
                __half2 hh;
                hh = __floats2half2_rn(p00, p01); pf[j][0] = *reinterpret_cast<unsigned*>(&hh);
                hh = __floats2half2_rn(p02, p03); pf[j][1] = *reinterpret_cast<unsigned*>(&hh);
                hh = __floats2half2_rn(p10, p11); pf[j][2] = *reinterpret_cast<unsigned*>(&hh);
                hh = __floats2half2_rn(p12, p13); pf[j][3] = *reinterpret_cast<unsigned*>(&hh);
            }

#pragma unroll
            for (int ks = 0; ks < 4; ++ks) {
#pragma unroll
                for (int ng = 0; ng < 4; ++ng) {
                    unsigned r0, r1, r2, r3;
                    ldsm_x4h_t(r0, r1, r2, r3,
                               &Vb[(ks * 16 + v_row) * ASTRH + ng * 16 + v_coff]);
                    mma_f16(o[ng * 2][0], o[ng * 2][1], o[ng * 2][2], o[ng * 2][3],
                            pf[ks][0], pf[ks][1], pf[ks][2], pf[ks][3], r0, r1);
                    mma_f16(o[ng * 2 + 1][0], o[ng * 2 + 1][1], o[ng * 2 + 1][2], o[ng * 2 + 1][3],
                            pf[ks][0], pf[ks][1], pf[ks][2], pf[ks][3], r2, r3);
                }
            }
        }
        __syncthreads();
    }

    l0 += __shfl_xor_sync(0xffffffffu, l0, 1);
    l0 += __shfl_xor_sync(0xffffffffu, l0, 2);
    l1 += __shfl_xor_sync(0xffffffffu, l1, 1);
    l1 += __shfl_xor_sync(0xffffffffu, l1, 2);
    float inv0 = 1.f / l0, inv1 = 1.f / l1;

    __half* ob0 = out + ((size_t)(t0 + prow0) * B_ + b) * D_ + h * 64 + pcol;
    __half* ob1 = out + ((size_t)(t0 + prow0 + 8) * B_ + b) * D_ + h * 64 + pcol;
#pragma unroll
    for (int n = 0; n < 8; ++n) {
        *reinterpret_cast<__half2*>(ob0 + n * 8) = __floats2half2_rn(o[n][0] * inv0, o[n][1] * inv0);
        *reinterpret_cast<__half2*>(ob1 + n * 8) = __floats2half2_rn(o[n][2] * inv1, o[n][3] * inv1);
    }
}

// ---------------------------------------------------------------------------
// FP16 banded sliding-window attention (register P, exp2 softmax).
// ---------------------------------------------------------------------------
#define KBUFH (64 * ASTRH)
#define SWA_SMEM ((128 + 4 * 64) * ASTRH * 2)

__global__ void __launch_bounds__(256, 2) sw_attn_f16_kernel(
    const __half* __restrict__ q, const __half* __restrict__ kv,
    __half* __restrict__ out)
{
    extern __shared__ __half smh[];
    __half* Ps = smh;
    __half* Ks = smh + 128 * ASTRH;
    __half* Vs = Ks + 2 * KBUFH;

    const int tid = threadIdx.x;
    const int wid = tid >> 5;
    const int lane = tid & 31;
    const int b = blockIdx.y >> 3;
    const int h = blockIdx.y & 7;
    const int t0 = blockIdx.x * 128;
    const int wm = wid * 16;

#pragma unroll
    for (int i = 0; i < 4; ++i) {
        int idx = i * 256 + tid;
        int r = idx >> 3, c = (idx & 7) * 8;
        cp_async16(&Ps[r * ASTRH + c],
                   q + ((size_t)(t0 + r) * B_ + b) * D_ + h * 64 + c);
    }
    {
        int key0 = t0 - 16;
#pragma unroll
        for (int i = 0; i < 2; ++i) {
            int idx = i * 256 + tid;
            int r = idx >> 3, c = (idx & 7) * 8;
            int key = min(max(key0 + r, 0), S_ - 1);
            const __half* base = kv + ((size_t)key * B_ + b) * 1024 + h * 64;
            cp_async16(&Ks[r * ASTRH + c], base + c);
            cp_async16(&Vs[r * ASTRH + c], base + 512 + c);
        }
    }
    cp_commit();
    cp_wait0();
    __syncthreads();

    unsigned qf[4][4];
    {
        const __half2 sc2 = __float2half2_rn(SCALE_ * LOG2E_);
        const int qrow = wm + (lane & 15);
        const int qko = (lane >> 4) * 8;
#pragma unroll
        for (int ks = 0; ks < 4; ++ks) {
            unsigned r0, r1, r2, r3;
            ldsm_x4h(r0, r1, r2, r3, &Ps[qrow * ASTRH + ks * 16 + qko]);
            unsigned rr[4] = {r0, r1, r2, r3};
#pragma unroll
            for (int j = 0; j < 4; ++j) {
                __half2 v = *reinterpret_cast<__half2*>(&rr[j]);
                v = __hmul2(v, sc2);
                qf[ks][j] = *reinterpret_cast<unsigned*>(&v);
            }
        }
    }

    float o[8][4];
#pragma unroll
    for (int n = 0; n < 8; ++n)
#pragma unroll
        for (int c = 0; c < 4; ++c) o[n][c] = 0.f;
    float m0 = -1e30f, m1 = -1e30f, l0 = 0.f, l1 = 0.f;

    const int brow_base = (lane & 7) + ((lane >> 4) * 8);
    const int bko = ((lane >> 3) & 1) * 8;
    const int prow0 = wm + (lane >> 2);
    const int pcol = 2 * (lane & 3);
    const int v_row = lane & 15;
    const int v_coff = (lane >> 4) * 8;

    for (int kt = 0; kt < 3; ++kt) {
        const int buf = kt & 1;
        const int key0 = t0 - 16 + kt * 64;

        if (kt + 1 < 3) {
            int nk0 = t0 - 16 + (kt + 1) * 64;
            __half* kd = Ks + (buf ^ 1) * KBUFH;
            __half* vd = Vs + (buf ^ 1) * KBUFH;
#pragma unroll
            for (int i = 0; i < 2; ++i) {
                int idx = i * 256 + tid;
                int r = idx >> 3, c = (idx & 7) * 8;
                int key = min(max(nk0 + r, 0), S_ - 1);
                const __half* base = kv + ((size_t)key * B_ + b) * 1024 + h * 64;
                cp_async16(&kd[r * ASTRH + c], base + c);
                cp_async16(&vd[r * ASTRH + c], base + 512 + c);
            }
            cp_commit();
            cp_wait1();
        } else {
            cp_wait0();
        }
        __syncthreads();

        const __half* Kb = Ks + buf * KBUFH;
        float s[8][4];
#pragma unroll
        for (int n = 0; n < 8; ++n)
#pragma unroll
            for (int c = 0; c < 4; ++c) s[n][c] = 0.f;
#pragma unroll
        for (int ks = 0; ks < 4; ++ks) {
#pragma unroll
            for (int ng = 0; ng < 4; ++ng) {
                unsigned r0, r1, r2, r3;
                ldsm_x4h(r0, r1, r2, r3, &Kb[(brow_base + ng * 16) * ASTRH + ks * 16 + bko]);
                mma_f16(s[ng * 2][0], s[ng * 2][1], s[ng * 2][2], s[ng * 2][3],
                        qf[ks][0], qf[ks][1], qf[ks][2], qf[ks][3], r0, r1);
                mma_f16(s[ng * 2 + 1][0], s[ng * 2 + 1][1], s[ng * 2 + 1][2], s[ng * 2 + 1][3],
                        qf[ks][0], qf[ks][1], qf[ks][2], qf[ks][3], r2, r3);
            }
        }

#pragma unroll
        for (int n = 0; n < 8; ++n) {
#pragma unroll
            for (int c = 0; c < 4; ++c) {
                int key = key0 + n * 8 + pcol + (c & 1);
                int qg = t0 + prow0 + ((c >> 1) * 8);
                bool valid = (key >= 0) && (key < S_) && (key - qg <= W_) && (qg - key <= W_);
                if (!valid) s[n][c] = -1e38f;
            }
        }

        float mx0 = -1e30f, mx1 = -1e30f;
#pragma unroll
        for (int n = 0; n < 8; ++n) {
            mx0 = fmaxf(mx0, fmaxf(s[n][0], s[n][1]));
            mx1 = fmaxf(mx1, fmaxf(s[n][2], s[n][3]));
        }
        mx0 = fmaxf(mx0, __shfl_xor_sync(0xffffffffu, mx0, 1));
        mx0 = fmaxf(mx0, __shfl_xor_sync(0xffffffffu, mx0, 2));
        mx1 = fmaxf(mx1, __shfl_xor_sync(0xffffffffu, mx1, 1));
        mx1 = fmaxf(mx1, __shfl_xor_sync(0xffffffffu, mx1, 2));

        float mn0 = fmaxf(m0, mx0), mn1 = fmaxf(m1, mx1);
        float corr0 = exp2f(m0 - mn0), corr1 = exp2f(m1 - mn1);
        m0 = mn0; m1 = mn1;
        l0 *= corr0; l1 *= corr1;
#pragma unroll
        for (int n = 0; n < 8; ++n) {
            o[n][0] *= corr0; o[n][1] *= corr0;
            o[n][2] *= corr1; o[n][3] *= corr1;
        }

        unsigned pf[4][4];
#pragma unroll
        for (int j = 0; j < 4; ++j) {
            float p00 = exp2f(s[2 * j][0] - mn0);
            float p01 = exp2f(s[2 * j][1] - mn0);
            float p02 = exp2f(s[2 * j][2] - mn1);
            float p03 = exp2f(s[2 * j][3] - mn1);
            float p10 = exp2f(s[2 * j + 1][0] - mn0);
            float p11 = exp2f(s[2 * j + 1][1] - mn0);
            float p12 = exp2f(s[2 * j + 1][2] - mn1);
            float p13 = exp2f(s[2 * j + 1][3] - mn1);
            l0 += p00 + p01 + p10 + p11;
            l1 += p02 + p03 + p12 + p13;
            __half2 hh;
            hh = __floats2half2_rn(p00, p01); pf[j][0] = *reinterpret_cast<unsigned*>(&hh);
            hh = __floats2half2_rn(p02, p03); pf[j][1] = *reinterpret_cast<unsigned*>(&hh);
            hh = __floats2half2_rn(p10, p11); pf[j][2] = *reinterpret_cast<unsigned*>(&hh);
            hh = __floats2half2_rn(p12, p13); pf[j][3] = *reinterpret_cast<unsigned*>(&hh);
        }

        const __half* Vb = Vs + buf * KBUFH;
#pragma unroll
        for (int ks = 0; ks < 4; ++ks) {
#pragma unroll
            for (int ng = 0; ng < 4; ++ng) {
                unsigned r0, r1, r2, r3;
                ldsm_x4h_t(r0, r1, r2, r3,
                           &Vb[(ks * 16 + v_row) * ASTRH + ng * 16 + v_coff]);
                mma_f16(o[ng * 2][0], o[ng * 2][1], o[ng * 2][2], o[ng * 2][3],
                        pf[ks][0], pf[ks][1], pf[ks][2], pf[ks][3], r0, r1);
                mma_f16(o[ng * 2 + 1][0], o[ng * 2 + 1][1], o[ng * 2 + 1][2], o[ng * 2 + 1][3],
                        pf[ks][0], pf[ks][1], pf[ks][2], pf[ks][3], r2, r3);
            }
        }
        __syncthreads();
    }

    l0 += __shfl_xor_sync(0xffffffffu, l0, 1);
    l0 += __shfl_xor_sync(0xffffffffu, l0, 2);
    l1 += __shfl_xor_sync(0xffffffffu, l1, 1);
    l1 += __shfl_xor_sync(0xffffffffu, l1, 2);
    float inv0 = 1.f / l0, inv1 = 1.f / l1;

    __half* ob0 = out + ((size_t)(t0 + prow0) * B_ + b) * D_ + h * 64 + pcol;
    __half* ob1 = out + ((size_t)(t0 + prow0 + 8) * B_ + b) * D_ + h * 64 + pcol;
#pragma unroll
    for (int n = 0; n < 8; ++n) {
        *reinterpret_cast<__half2*>(ob0 + n * 8) = __floats2half2_rn(o[n][0] * inv0, o[n][1] * inv0);
        *reinterpret_cast<__half2*>(ob1 + n * 8) = __floats2half2_rn(o[n][2] * inv1, o[n][3] * inv1);
    }
}

// ---------------------------------------------------------------------------
// Fused residual-add(y fp16) + LayerNorm, single-pass.
// ---------------------------------------------------------------------------
__global__ void __launch_bounds__(256) add_ln_h_kernel(
    const float* __restrict__ x, const __half* __restrict__ y,
    const float* __restrict__ g, const float* __restrict__ beta,
    float* __restrict__ out, __half* __restrict__ out16)
{
    __shared__ float shs[8];
    __shared__ float shq[8];
    __shared__ float sres[2];
    const int row = blockIdx.x;
    const int tid = threadIdx.x;
    const size_t base = (size_t)row * D_;

    float v0 = x[base + tid] + __half2float(y[base + tid]);
    float v1 = x[base + tid + 256] + __half2float(y[base + tid + 256]);

    float s = v0 + v1;
    float sq = v0 * v0 + v1 * v1;
#pragma unroll
    for (int o = 16; o > 0; o >>= 1) {
        s  += __shfl_xor_sync(0xffffffffu, s, o);
        sq += __shfl_xor_sync(0xffffffffu, sq, o);
    }
    int lane = tid & 31, wid = tid >> 5;
    if (lane == 0) { shs[wid] = s; shq[wid] = sq; }
    __syncthreads();
    if (wid == 0) {
        float ts = (lane < 8) ? shs[lane] : 0.f;
        float tq = (lane < 8) ? shq[lane] : 0.f;
#pragma unroll
        for (int o = 4; o > 0; o >>= 1) {
            ts += __shfl_xor_sync(0xffffffffu, ts, o);
            tq += __shfl_xor_sync(0xffffffffu, tq, o);
        }
        if (lane == 0) {
            float mean = ts * (1.f / D_);
            float var = tq * (1.f / D_) - mean * mean;
            sres[0] = mean;
            sres[1] = rsqrtf(var + EPS_);
        }
    }
    __syncthreads();
    float mean = sres[0];
    float rstd = sres[1];

    float r0 = (v0 - mean) * rstd * g[tid] + beta[tid];
    float r1 = (v1 - mean) * rstd * g[tid + 256] + beta[tid + 256];
    out[base + tid] = r0;
    out[base + tid + 256] = r1;
    if (out16) {
        out16[base + tid] = __float2half_rn(r0);
        out16[base + tid + 256] = __float2half_rn(r1);
    }
}

// ---------------------------------------------------------------------------
// Launch
// ---------------------------------------------------------------------------
extern "C" void kernel_launch(void* const* d_in, const int* in_sizes, int n_in,
                              void* d_out, int out_size)
{
    (void)in_sizes; (void)n_in; (void)out_size;
    const float* tgt        = (const float*)d_in[0];
    const float* memory     = (const float*)d_in[1];
    const float* in_proj_w  = (const float*)d_in[2];
    const float* in_proj_b  = (const float*)d_in[3];
    const float* out_proj_w = (const float*)d_in[4];
    const float* out_proj_b = (const float*)d_in[5];
    const float* sw_q_w = (const float*)d_in[6];
    const float* sw_q_b = (const float*)d_in[7];
    const float* sw_k_w = (const float*)d_in[8];
    const float* sw_k_b = (const float*)d_in[9];
    const float* sw_v_w = (const float*)d_in[10];
    const float* sw_v_b = (const float*)d_in[11];
    const float* sw_o_w = (const float*)d_in[12];
    const float* sw_o_b = (const float*)d_in[13];
    const float* lin1_w = (const float*)d_in[14];
    const float* lin1_b = (const float*)d_in[15];
    const float* lin2_w = (const float*)d_in[16];
    const float* lin2_b = (const float*)d_in[17];
    const float* n1_g = (const float*)d_in[18];
    const float* n1_b = (const float*)d_in[19];
    const float* n2_g = (const float*)d_in[20];
    const float* n2_b = (const float*)d_in[21];
    const float* n3_g = (const float*)d_in[22];
    const float* n3_b = (const float*)d_in[23];
    float* out = (float*)d_out;

    float* s = nullptr;
    cudaGetSymbolAddress((void**)&s, g_scratch);
    float* x1   = s + FOFF_X1;
    float* x2   = s + FOFF_X2;
    float* bcat = s + FOFF_BCAT;
    __half* hb = (__half*)(s + HALF_BASE_F);
    __half* qkv16    = hb + HOFF_QKV;
    __half* attn16   = hb + HOFF_ATTN;
    __half* swq16    = hb + HOFF_SWQ;
    __half* swkv16   = hb + HOFF_SWKV;
    __half* swattn16 = hb + HOFF_SWATTN;
    __half* hbuf16   = hb + HOFF_HBUF;
    __half* tgt16    = hb + HOFF_TGT;
    __half* mem16    = hb + HOFF_MEM;
    __half* x1h      = hb + HOFF_X1H;
    __half* x2h      = hb + HOFF_X2H;
    __half* w_in     = hb + HOFF_WIN;
    __half* w_out    = hb + HOFF_WOUT;
    __half* w_swq    = hb + HOFF_WSWQ;
    __half* w_swkv   = hb + HOFF_WSWKV;
    __half* w_swo    = hb + HOFF_WSWO;
    __half* w_lin1   = hb + HOFF_WLIN1;
    __half* w_lin2   = hb + HOFF_WLIN2;
    __half* proj16   = hb + HOFF_PROJ16;
    __half* ff16     = hb + HOFF_FF16;

    cudaFuncSetAttribute(self_attn_f16_kernel,
                         cudaFuncAttributeMaxDynamicSharedMemorySize, ATTN_SMEM);
    cudaFuncSetAttribute(sw_attn_f16_kernel,
                         cudaFuncAttributeMaxDynamicSharedMemorySize, SWA_SMEM);
    cudaFuncSetAttribute(gemm_f16_kernel,
                         cudaFuncAttributeMaxDynamicSharedMemorySize, G128_SMEM);
    cudaFuncSetAttribute(gemm_f16_dual_kernel,
                         cudaFuncAttributeMaxDynamicSharedMemorySize, G128_SMEM);
    cudaFuncSetAttribute(gemm_f16_n64_kernel,
                         cudaFuncAttributeMaxDynamicSharedMemorySize, G64_SMEM);

    // one fused convert (incl. KV weight concat + bias concat)
    f2h_multi_kernel<<<8192, 256>>>(tgt, tgt16, memory, mem16,
                                    in_proj_w, w_in, out_proj_w, w_out,
                                    sw_q_w, w_swq, sw_o_w, w_swo,
                                    lin1_w, w_lin1, lin2_w, w_lin2,
                                    sw_k_w, w_swkv, sw_v_w, w_swkv + 262144,
                                    sw_k_b, sw_v_b, bcat);

    // combined QKV (N=1536, 12 blocks) + fused KV (N=1024, 8 blocks)
    gemm_f16_dual_kernel<<<dim3(20, 32), 256, G128_SMEM>>>(
        tgt16, w_in, in_proj_b, qkv16, 3 * D_,
        mem16, w_swkv, bcat, swkv16, 1024,
        D_, 12);
    // self attention
    self_attn_f16_kernel<<<dim3(8, 32), 256, ATTN_SMEM>>>(qkv16, attn16);
    // out projection -> fp16
    gemm_f16_n64_kernel<<<dim3(8, 32), 256, G64_SMEM>>>(attn16, w_out, out_proj_b, proj16,
                                                        NROWS, D_, D_, 0, 1);
    // add + LN1
    add_ln_h_kernel<<<NROWS, 256>>>(tgt, proj16, n1_g, n1_b, x1, x1h);
    // sw q projection
    gemm_f16_n64_kernel<<<dim3(8, 32), 256, G64_SMEM>>>(x1h, w_swq, sw_q_b, swq16,
                                                        NROWS, D_, D_, 0, 1);
    // banded attention
    sw_attn_f16_kernel<<<dim3(8, 32), 256, SWA_SMEM>>>(swq16, swkv16, swattn16);
    // sw out projection -> fp16
    gemm_f16_n64_kernel<<<dim3(8, 32), 256, G64_SMEM>>>(swattn16, w_swo, sw_o_b, proj16,
                                                        NROWS, D_, D_, 0, 1);
    // add + LN2
    add_ln_h_kernel<<<NROWS, 256>>>(x1, proj16, n2_g, n2_b, x2, x2h);
    // FFN up + ReLU
    gemm_f16_kernel<<<dim3(16, 32), 256, G128_SMEM>>>(x2h, w_lin1, lin1_b, hbuf16,
                                                      NROWS, DFF_, D_, 1, 1);
    // FFN down -> fp16
    gemm_f16_n64_kernel<<<dim3(8, 32), 256, G64_SMEM>>>(hbuf16, w_lin2, lin2_b, ff16,
                                                        NROWS, D_, DFF_, 0, 1);
    // add + LN3 -> output (fp32 only)
    add_ln_h_kernel<<<NROWS, 256>>>(x2, ff16, n3_g, n3_b, out, nullptr);
}

// round 15
// speedup vs baseline: 1.0309x; 1.0309x over previous
#include <cuda_runtime.h>
#include <cuda_fp16.h>
#include <stdint.h>
#include <math.h>

#define T_ 1024
#define S_ 1024
#define B_ 4
#define D_ 512
#define H_ 8
#define HD_ 64
#define DFF_ 2048
#define W_ 16
#define NROWS (T_ * B_)
#define SCALE_ 0.125f
#define LOG2E_ 1.4426950408889634f
#define EPS_ 1e-5f

// fp32 region (float offsets)
#define FOFF_X1     0
#define FOFF_X2     2097152
#define FOFF_BCAT   4194304
#define HALF_BASE_F 5000000

// half region (half offsets)
#define HOFF_QKV    0
#define HOFF_ATTN   6291456
#define HOFF_SWQ    8388608
#define HOFF_SWKV   10485760
#define HOFF_SWATTN 14680064
#define HOFF_HBUF   16777216
#define HOFF_TGT    25165824
#define HOFF_MEM    27262976
#define HOFF_X1H    29360128
#define HOFF_X2H    31457280
#define HOFF_WIN    33554432
#define HOFF_WOUT   34340864
#define HOFF_WSWQ   34603008
#define HOFF_WSWKV  34865152
#define HOFF_WSWO   35389440
#define HOFF_WLIN1  35651584
#define HOFF_WLIN2  36700160
#define HOFF_PROJ16 37748736
#define HOFF_FF16   39845888

#define SCRATCH_FLOATS 33554432
__device__ float g_scratch[SCRATCH_FLOATS];

// ---------------------------------------------------------------------------
// PTX helpers
// ---------------------------------------------------------------------------
__device__ __forceinline__ void cp_async16(void* smem_ptr, const void* gmem_ptr) {
    unsigned saddr = (unsigned)__cvta_generic_to_shared(smem_ptr);
    asm volatile("cp.async.cg.shared.global [%0], [%1], 16;\n"
                 :: "r"(saddr), "l"(gmem_ptr));
}
__device__ __forceinline__ void cp_commit() {
    asm volatile("cp.async.commit_group;\n");
}
__device__ __forceinline__ void cp_wait0() {
    asm volatile("cp.async.wait_group 0;\n");
}
__device__ __forceinline__ void cp_wait1() {
    asm volatile("cp.async.wait_group 1;\n");
}
__device__ __forceinline__ void ldsm_x4h(unsigned& r0, unsigned& r1, unsigned& r2, unsigned& r3,
                                         const __half* p) {
    unsigned saddr = (unsigned)__cvta_generic_to_shared((void*)p);
    asm volatile("ldmatrix.sync.aligned.m8n8.x4.shared.b16 {%0,%1,%2,%3}, [%4];\n"
                 : "=r"(r0), "=r"(r1), "=r"(r2), "=r"(r3) : "r"(saddr));
}
__device__ __forceinline__ void ldsm_x4h_t(unsigned& r0, unsigned& r1, unsigned& r2, unsigned& r3,
                                           const __half* p) {
    unsigned saddr = (unsigned)__cvta_generic_to_shared((void*)p);
    asm volatile("ldmatrix.sync.aligned.m8n8.x4.trans.shared.b16 {%0,%1,%2,%3}, [%4];\n"
                 : "=r"(r0), "=r"(r1), "=r"(r2), "=r"(r3) : "r"(saddr));
}
__device__ __forceinline__ void mma_f16(float& c0, float& c1, float& c2, float& c3,
                                        unsigned a0, unsigned a1, unsigned a2, unsigned a3,
                                        unsigned b0, unsigned b1) {
    asm volatile("mma.sync.aligned.m16n8k16.row.col.f32.f16.f16.f32 "
                 "{%0,%1,%2,%3}, {%4,%5,%6,%7}, {%8,%9}, {%0,%1,%2,%3};\n"
                 : "+f"(c0), "+f"(c1), "+f"(c2), "+f"(c3)
                 : "r"(a0), "r"(a1), "r"(a2), "r"(a3), "r"(b0), "r"(b1));
}

// ---------------------------------------------------------------------------
// fp32->fp16 fused convert: 10 segments incl. KV weight concat + bias copy.
// ---------------------------------------------------------------------------
__global__ void __launch_bounds__(256) f2h_multi_kernel(
    const float* __restrict__ s0, __half* __restrict__ d0,
    const float* __restrict__ s1, __half* __restrict__ d1,
    const float* __restrict__ s2, __half* __restrict__ d2,
    const float* __restrict__ s3, __half* __restrict__ d3,
    const float* __restrict__ s4, __half* __restrict__ d4,
    const float* __restrict__ s5, __half* __restrict__ d5,
    const float* __restrict__ s6, __half* __restrict__ d6,
    const float* __restrict__ s7, __half* __restrict__ d7,
    const float* __restrict__ s8, __half* __restrict__ d8,
    const float* __restrict__ s9, __half* __restrict__ d9,
    const float* __restrict__ kb, const float* __restrict__ vb,
    float* __restrict__ bcat)
{
    if (blockIdx.x == 0) {
        int t = threadIdx.x;
        bcat[t] = kb[t];          bcat[512 + t] = vb[t];
        bcat[256 + t] = kb[256 + t]; bcat[768 + t] = vb[256 + t];
    }
    int idx = (blockIdx.x * 256 + threadIdx.x) * 4;
    const float* src; __half* dst; int off;
    if      (idx < 2097152) { src = s0; dst = d0; off = idx; }
    else if (idx < 4194304) { src = s1; dst = d1; off = idx - 2097152; }
    else if (idx < 4980736) { src = s2; dst = d2; off = idx - 4194304; }
    else if (idx < 5242880) { src = s3; dst = d3; off = idx - 4980736; }
    else if (idx < 5505024) { src = s4; dst = d4; off = idx - 5242880; }
    else if (idx < 5767168) { src = s5; dst = d5; off = idx - 5505024; }
    else if (idx < 6815744) { src = s6; dst = d6; off = idx - 5767168; }
    else if (idx < 7864320) { src = s7; dst = d7; off = idx - 6815744; }
    else if (idx < 8126464) { src = s8; dst = d8; off = idx - 7864320; }
    else                    { src = s9; dst = d9; off = idx - 8126464; }
    float4 v = *reinterpret_cast<const float4*>(src + off);
    *reinterpret_cast<__half2*>(dst + off)     = __floats2half2_rn(v.x, v.y);
    *reinterpret_cast<__half2*>(dst + off + 2) = __floats2half2_rn(v.z, v.w);
}

// ---------------------------------------------------------------------------
// FP16 GEMM 128x128 core, BK=64, 3-stage pipeline.
// ---------------------------------------------------------------------------
#define STR64 72
#define ASTG (128 * STR64)
#define G128_SMEM (6 * ASTG * 2)

__device__ __forceinline__ void gemm128_body(
    const __half* __restrict__ A, const __half* __restrict__ Wt,
    const float* __restrict__ bias, void* __restrict__ Cout,
    int N, int K, int relu, int out16, int m0, int n0, __half* sg)
{
    __half* As = sg;
    __half* Bs = sg + 3 * ASTG;

    const int tid  = threadIdx.x;
    const int wid  = tid >> 5;
    const int lane = tid & 31;
    const int wm   = (wid & 3) * 32;
    const int wn   = (wid >> 2) * 64;

    float acc[2][8][4];
#pragma unroll
    for (int i = 0; i < 2; ++i)
#pragma unroll
        for (int j = 0; j < 8; ++j)
#pragma unroll
            for (int q = 0; q < 4; ++q) acc[i][j][q] = 0.f;

    const int ntiles = K / 64;
    const __half* Abase = A + (size_t)m0 * K;
    const __half* Bbase = Wt + (size_t)n0 * K;

    auto load_stage = [&](int t, int st) {
        int k0 = t * 64;
        __half* Ad = As + st * ASTG;
        __half* Bd = Bs + st * ASTG;
#pragma unroll
        for (int it = 0; it < 4; ++it) {
            int idx = it * 256 + tid;
            int row = idx >> 3, col = (idx & 7) * 8;
            cp_async16(&Ad[row * STR64 + col], Abase + (size_t)row * K + k0 + col);
            cp_async16(&Bd[row * STR64 + col], Bbase + (size_t)row * K + k0 + col);
        }
    };

    load_stage(0, 0); cp_commit();
    load_stage(1, 1); cp_commit();

    const int a_row = wm + (lane & 15);
    const int a_koff = (lane >> 4) * 8;
    const int b_row_base = wn + (lane & 7) + ((lane >> 4) * 8);
    const int b_koff = ((lane >> 3) & 1) * 8;

    for (int t = 0; t < ntiles; ++t) {
        cp_wait1();
        __syncthreads();

        int ps = t + 2;
        if (ps < ntiles) load_stage(ps, ps % 3);
        cp_commit();

        const int buf = t % 3;
        const __half* Ab = As + buf * ASTG;
        const __half* Bb = Bs + buf * ASTG;
#pragma unroll
        for (int ks = 0; ks < 4; ++ks) {
            unsigned a[2][4];
            unsigned b[8][2];
#pragma unroll
            for (int im = 0; im < 2; ++im)
                ldsm_x4h(a[im][0], a[im][1], a[im][2], a[im][3],
                         &Ab[(a_row + im * 16) * STR64 + ks * 16 + a_koff]);
#pragma unroll
            for (int ng = 0; ng < 4; ++ng) {
                unsigned r0, r1, r2, r3;
                ldsm_x4h(r0, r1, r2, r3,
                         &Bb[(b_row_base + ng * 16) * STR64 + ks * 16 + b_koff]);
                b[ng * 2][0] = r0; b[ng * 2][1] = r1;
                b[ng * 2 + 1][0] = r2; b[ng * 2 + 1][1] = r3;
            }
#pragma unroll
            for (int im = 0; im < 2; ++im)
#pragma unroll
                for (int in = 0; in < 8; ++in)
                    mma_f16(acc[im][in][0], acc[im][in][1], acc[im][in][2], acc[im][in][3],
                            a[im][0], a[im][1], a[im][2], a[im][3],
                            b[in][0], b[in][1]);
        }
    }

    const int row_base = m0 + wm + (lane >> 2);
    const int col_base = n0 + wn + (lane & 3) * 2;
#pragma unroll
    for (int im = 0; im < 2; ++im) {
#pragma unroll
        for (int in = 0; in < 8; ++in) {
            int col = col_base + in * 8;
            float b0 = bias[col], b1 = bias[col + 1];
            int r0 = row_base + im * 16;
            float v0 = acc[im][in][0] + b0;
            float v1 = acc[im][in][1] + b1;
            float v2 = acc[im][in][2] + b0;
            float v3 = acc[im][in][3] + b1;
            if (relu) {
                v0 = fmaxf(v0, 0.f); v1 = fmaxf(v1, 0.f);
                v2 = fmaxf(v2, 0.f); v3 = fmaxf(v3, 0.f);
            }
            if (out16) {
                __half* C = (__half*)Cout;
                *reinterpret_cast<__half2*>(&C[(size_t)r0 * N + col]) = __floats2half2_rn(v0, v1);
                *reinterpret_cast<__half2*>(&C[(size_t)(r0 + 8) * N + col]) = __floats2half2_rn(v2, v3);
            } else {
                float* C = (float*)Cout;
                C[(size_t)r0 * N + col] = v0;
                C[(size_t)r0 * N + col + 1] = v1;
                C[(size_t)(r0 + 8) * N + col] = v2;
                C[(size_t)(r0 + 8) * N + col + 1] = v3;
            }
        }
    }
}

__global__ void __launch_bounds__(256, 2) gemm_f16_kernel(
    const __half* __restrict__ A, const __half* __restrict__ Wt,
    const float* __restrict__ bias, void* __restrict__ Cout,
    int M, int N, int K, int relu, int out16)
{
    extern __shared__ __half sg[];
    gemm128_body(A, Wt, bias, Cout, N, K, relu, out16,
                 blockIdx.y * 128, blockIdx.x * 128, sg);
}

__global__ void __launch_bounds__(256, 2) gemm_f16_dual_kernel(
    const __half* __restrict__ A1, const __half* __restrict__ W1,
    const float* __restrict__ b1, void* __restrict__ C1, int N1,
    const __half* __restrict__ A2, const __half* __restrict__ W2,
    const float* __restrict__ b2, void* __restrict__ C2, int N2,
    int K, int split)
{
    extern __shared__ __half sg[];
    if ((int)blockIdx.x < split)
        gemm128_body(A1, W1, b1, C1, N1, K, 0, 1,
                     blockIdx.y * 128, blockIdx.x * 128, sg);
    else
        gemm128_body(A2, W2, b2, C2, N2, K, 0, 1,
                     blockIdx.y * 128, (blockIdx.x - split) * 128, sg);
}

// ---------------------------------------------------------------------------
// FP16 GEMM 128x64, BK=64, 3-stage.
// ---------------------------------------------------------------------------
#define BSTG64 (64 * STR64)
#define G64_SMEM ((3 * ASTG + 3 * BSTG64) * 2)

__global__ void __launch_bounds__(256, 2) gemm_f16_n64_kernel(
    const __half* __restrict__ A, const __half* __restrict__ Wt,
    const float* __restrict__ bias, void* __restrict__ Cout,
    int M, int N, int K, int relu, int out16)
{
    extern __shared__ __half sg[];
    __half* As = sg;
    __half* Bs = sg + 3 * ASTG;

    const int tid  = threadIdx.x;
    const int wid  = tid >> 5;
    const int lane = tid & 31;
    const int wm   = (wid & 3) * 32;
    const int wn   = (wid >> 2) * 32;
    const int m0   = blockIdx.y * 128;
    const int n0   = blockIdx.x * 64;

    float acc[2][4][4];
#pragma unroll
    for (int i = 0; i < 2; ++i)
#pragma unroll
        for (int j = 0; j < 4; ++j)
#pragma unroll
            for (int q = 0; q < 4; ++q) acc[i][j][q] = 0.f;

    const int ntiles = K / 64;
    const __half* Abase = A + (size_t)m0 * K;
    const __half* Bbase = Wt + (size_t)n0 * K;

    auto load_stage = [&](int t, int st) {
        int k0 = t * 64;
        __half* Ad = As + st * ASTG;
        __half* Bd = Bs + st * BSTG64;
#pragma unroll
        for (int it = 0; it < 4; ++it) {
            int idx = it * 256 + tid;
            int row = idx >> 3, col = (idx & 7) * 8;
            cp_async16(&Ad[row * STR64 + col], Abase + (size_t)row * K + k0 + col);
        }
#pragma unroll
        for (int it = 0; it < 2; ++it) {
            int idx = it * 256 + tid;
            int row = idx >> 3, col = (idx & 7) * 8;
            cp_async16(&Bd[row * STR64 + col], Bbase + (size_t)row * K + k0 + col);
        }
    };

    load_stage(0, 0); cp_commit();
    load_stage(1, 1); cp_commit();

    const int a_row = wm + (lane & 15);
    const int a_koff = (lane >> 4) * 8;
    const int b_row_base = wn + (lane & 7) + ((lane >> 4) * 8);
    const int b_koff = ((lane >> 3) & 1) * 8;

    for (int t = 0; t < ntiles; ++t) {
        cp_wait1();
        __syncthreads();

        int ps = t + 2;
        if (ps < ntiles) load_stage(ps, ps % 3);
        cp_commit();

        const int buf = t % 3;
        const __half* Ab = As + buf * ASTG;
        const __half* Bb = Bs + buf * BSTG64;
#pragma unroll
        for (int ks = 0; ks < 4; ++ks) {
            unsigned a[2][4];
            unsigned b[4][2];
#pragma unroll
            for (int im = 0; im < 2; ++im)
                ldsm_x4h(a[im][0], a[im][1], a[im][2], a[im][3],
                         &Ab[(a_row + im * 16) * STR64 + ks * 16 + a_koff]);
#pragma unroll
            for (int ng = 0; ng < 2; ++ng) {
                unsigned r0, r1, r2, r3;
                ldsm_x4h(r0, r1, r2, r3,
                         &Bb[(b_row_base + ng * 16) * STR64 + ks * 16 + b_koff]);
                b[ng * 2][0] = r0; b[ng * 2][1] = r1;
                b[ng * 2 + 1][0] = r2; b[ng * 2 + 1][1] = r3;
            }
#pragma unroll
            for (int im = 0; im < 2; ++im)
#pragma unroll
                for (int in = 0; in < 4; ++in)
                    mma_f16(acc[im][in][0], acc[im][in][1], acc[im][in][2], acc[im][in][3],
                            a[im][0], a[im][1], a[im][2], a[im][3],
                            b[in][0], b[in][1]);
        }
    }

    const int row_base = m0 + wm + (lane >> 2);
    const int col_base = n0 + wn + (lane & 3) * 2;
#pragma unroll
    for (int im = 0; im < 2; ++im) {
#pragma unroll
        for (int in = 0; in < 4; ++in) {
            int col = col_base + in * 8;
            float b0 = bias[col], b1 = bias[col + 1];
            int r0 = row_base + im * 16;
            float v0 = acc[im][in][0] + b0;
            float v1 = acc[im][in][1] + b1;
            float v2 = acc[im][in][2] + b0;
            float v3 = acc[im][in][3] + b1;
            if (relu) {
                v0 = fmaxf(v0, 0.f); v1 = fmaxf(v1, 0.f);
                v2 = fmaxf(v2, 0.f); v3 = fmaxf(v3, 0.f);
            }
            if (out16) {
                __half* C = (__half*)Cout;
                *reinterpret_cast<__half2*>(&C[(size_t)r0 * N + col]) = __floats2half2_rn(v0, v1);
                *reinterpret_cast<__half2*>(&C[(size_t)(r0 + 8) * N + col]) = __floats2half2_rn(v2, v3);
            } else {
                float* C = (float*)Cout;
                C[(size_t)r0 * N + col] = v0;
                C[(size_t)r0 * N + col + 1] = v1;
                C[(size_t)(r0 + 8) * N + col] = v2;
                C[(size_t)(r0 + 8) * N + col + 1] = v3;
            }
        }
    }
}

// ---------------------------------------------------------------------------
// FP16 flash self-attention: 128-key tiles, register P, exp2 softmax.
// ---------------------------------------------------------------------------
#define ASTRH 72
#define KB128 (128 * ASTRH)
#define ROWH 6144
#define ATTN_SMEM ((128 + 4 * 128) * ASTRH * 2)

__global__ void __launch_bounds__(256, 2) self_attn_f16_kernel(
    const __half* __restrict__ qkv, __half* __restrict__ out)
{
    extern __shared__ __half smh[];
    __half* Ps = smh;
    __half* Ks = smh + 128 * ASTRH;
    __half* Vs = Ks + 2 * KB128;

    const int tid = threadIdx.x;
    const int wid = tid >> 5;
    const int lane = tid & 31;
    const int b = blockIdx.y >> 3;
    const int h = blockIdx.y & 7;
    const int t0 = blockIdx.x * 128;
    const int wm = wid * 16;

    const __half* qbase = qkv + ((size_t)t0 * B_ + b) * 1536 + h * 64;
    const __half* kroot = qkv + (size_t)b * 1536 + 512 + h * 64;
    const __half* vroot = qkv + (size_t)b * 1536 + 1024 + h * 64;

#pragma unroll
    for (int i = 0; i < 4; ++i) {
        int idx = i * 256 + tid;
        int r = idx >> 3, c = (idx & 7) * 8;
        cp_async16(&Ps[r * ASTRH + c], qbase + (size_t)r * ROWH + c);
    }
#pragma unroll
    for (int i = 0; i < 4; ++i) {
        int idx = i * 256 + tid;
        int r = idx >> 3, c = (idx & 7) * 8;
        cp_async16(&Ks[r * ASTRH + c], kroot + (size_t)r * ROWH + c);
        cp_async16(&Vs[r * ASTRH + c], vroot + (size_t)r * ROWH + c);
    }
    cp_commit();
    cp_wait0();
    __syncthreads();

    unsigned qf[4][4];
    {
        const __half2 sc2 = __float2half2_rn(SCALE_ * LOG2E_);
        const int qrow = wm + (lane & 15);
        const int qko = (lane >> 4) * 8;
#pragma unroll
        for (int ks = 0; ks < 4; ++ks) {
            unsigned r0, r1, r2, r3;
            ldsm_x4h(r0, r1, r2, r3, &Ps[qrow * ASTRH + ks * 16 + qko]);
            unsigned rr[4] = {r0, r1, r2, r3};
#pragma unroll
            for (int j = 0; j < 4; ++j) {
                __half2 v = *reinterpret_cast<__half2*>(&rr[j]);
                v = __hmul2(v, sc2);
                qf[ks][j] = *reinterpret_cast<unsigned*>(&v);
            }
        }
    }

    float o[8][4];
#pragma unroll
    for (int n = 0; n < 8; ++n)
#pragma unroll
        for (int c = 0; c < 4; ++c) o[n][c] = 0.f;
    float m0 = -1e30f, m1 = -1e30f, l0 = 0.f, l1 = 0.f;

    const int brow_base = (lane & 7) + ((lane >> 4) * 8);
    const int bko = ((lane >> 3) & 1) * 8;
    const int prow0 = wm + (lane >> 2);
    const int pcol = 2 * (lane & 3);
    const int v_row = lane & 15;
    const int v_coff = (lane >> 4) * 8;

    for (int kt = 0; kt < 8; ++kt) {
        const int buf = kt & 1;

        if (kt + 1 < 8) {
            const __half* kb = kroot + (size_t)(kt + 1) * 128 * ROWH;
            const __half* vb = vroot + (size_t)(kt + 1) * 128 * ROWH;
            __half* kd = Ks + (buf ^ 1) * KB128;
            __half* vd = Vs + (buf ^ 1) * KB128;
#pragma unroll
            for (int i = 0; i < 4; ++i) {
                int idx = i * 256 + tid;
                int r = idx >> 3, c = (idx & 7) * 8;
                cp_async16(&kd[r * ASTRH + c], kb + (size_t)r * ROWH + c);
                cp_async16(&vd[r * ASTRH + c], vb + (size_t)r * ROWH + c);
            }
            cp_commit();
            cp_wait1();
        } else {
            cp_wait0();
        }
        __syncthreads();

#pragma unroll
        for (int half = 0; half < 2; ++half) {
            const __half* Kb = Ks + buf * KB128 + half * 64 * ASTRH;
            const __half* Vb = Vs + buf * KB128 + half * 64 * ASTRH;

            float s[8][4];
#pragma unroll
            for (int n = 0; n < 8; ++n)
#pragma unroll
                for (int c = 0; c < 4; ++c) s[n][c] = 0.f;
#pragma unroll
            for (int ks = 0; ks < 4; ++ks) {
#pragma unroll
                for (int ng = 0; ng < 4; ++ng) {
                    unsigned r0, r1, r2, r3;
                    ldsm_x4h(r0, r1, r2, r3, &Kb[(brow_base + ng * 16) * ASTRH + ks * 16 + bko]);
                    mma_f16(s[ng * 2][0], s[ng * 2][1], s[ng * 2][2], s[ng * 2][3],
                            qf[ks][0], qf[ks][1], qf[ks][2], qf[ks][3], r0, r1);
                    mma_f16(s[ng * 2 + 1][0], s[ng * 2 + 1][1], s[ng * 2 + 1][2], s[ng * 2 + 1][3],
                            qf[ks][0], qf[ks][1], qf[ks][2], qf[ks][3], r2, r3);
                }
            }

            float mx0 = -1e30f, mx1 = -1e30f;
#pragma unroll
            for (int n = 0; n < 8; ++n) {
                mx0 = fmaxf(mx0, fmaxf(s[n][0], s[n][1]));
                mx1 = fmaxf(mx1, fmaxf(s[n][2], s[n][3]));
            }
            mx0 = fmaxf(mx0, __shfl_xor_sync(0xffffffffu, mx0, 1));
            mx0 = fmaxf(mx0, __shfl_xor_sync(0xffffffffu, mx0, 2));
            mx1 = fmaxf(mx1, __shfl_xor_sync(0xffffffffu, mx1, 1));
            mx1 = fmaxf(mx1, __shfl_xor_sync(0xffffffffu, mx1, 2));

            float mn0 = fmaxf(m0, mx0), mn1 = fmaxf(m1, mx1);
            float corr0 = exp2f(m0 - mn0), corr1 = exp2f(m1 - mn1);
            m0 = mn0; m1 = mn1;
            l0 *= corr0; l1 *= corr1;
#pragma unroll
            for (int n = 0; n < 8; ++n) {
                o[n][0] *= corr0; o[n][1] *= corr0;
                o[n][2] *= corr1; o[n][3] *= corr1;
            }

            unsigned pf[4][4];
#pragma unroll
            for (int j = 0; j < 4; ++j) {
                float p00 = exp2f(s[2 * j][0] - mn0);
                float p01 = exp2f(s[2 * j][1] - mn0);
                float p02 = exp2f(s[2 * j][2] - mn1);
                float p03 = exp2f(s[2 * j][3] - mn1);
                float p10 = exp2f(s[2 * j + 1][0] - mn0);
                float p11 = exp2f(s[2 * j + 1][1] - mn0);
                float p12 = exp2f(s[2 * j + 1][2] - mn1);
                float p13 = exp2f(s[2 * j + 1][3] - mn1);
                l0 += p00 + p01 + p10 + p11;
                l1 += p02 + p03 + p12 + p13;
                __half2 hh;
                hh = __floats2half2_rn(p00, p01); pf[j][0] = *reinterpret_cast<unsigned*>(&hh);
                hh = __floats2half2_rn(p02, p03); pf[j][1] = *reinterpret_cast<unsigned*>(&hh);
                hh = __floats2half2_rn(p10, p11); pf[j][2] = *reinterpret_cast<unsigned*>(&hh);
                hh = __floats2half2_rn(p12, p13); pf[j][3] = *reinterpret_cast<unsigned*>(&hh);
            }

#pragma unroll
            for (int ks = 0; ks < 4; ++ks) {
#pragma unroll
                for (int ng = 0; ng < 4; ++ng) {
                    unsigned r0, r1, r2, r3;
                    ldsm_x4h_t(r0, r1, r2, r3,
                               &Vb[(ks * 16 + v_row) * ASTRH + ng * 16 + v_coff]);
                    mma_f16(o[ng * 2][0], o[ng * 2][1], o[ng * 2][2], o[ng * 2][3],
                            pf[ks][0], pf[ks][1], pf[ks][2], pf[ks][3], r0, r1);
                    mma_f16(o[ng * 2 + 1][0], o[ng * 2 + 1][1], o[ng * 2 + 1][2], o[ng * 2 + 1][3],
                            pf[ks][0], pf[ks][1], pf[ks][2], pf[ks][3], r2, r3);
                }
            }
        }
        __syncthreads();
    }

    l0 += __shfl_xor_sync(0xffffffffu, l0, 1);
    l0 += __shfl_xor_sync(0xffffffffu, l0, 2);
    l1 += __shfl_xor_sync(0xffffffffu, l1, 1);
    l1 += __shfl_xor_sync(0xffffffffu, l1, 2);
    float inv0 = 1.f / l0, inv1 = 1.f / l1;

    __half* ob0 = out + ((size_t)(t0 + prow0) * B_ + b) * D_ + h * 64 + pcol;
    __half* ob1 = out + ((size_t)(t0 + prow0 + 8) * B_ + b) * D_ + h * 64 + pcol;
#pragma unroll
    for (int n = 0; n < 8; ++n) {
        *reinterpret_cast<__half2*>(ob0 + n * 8) = __floats2half2_rn(o[n][0] * inv0, o[n][1] * inv0);
        *reinterpret_cast<__half2*>(ob1 + n * 8) = __floats2half2_rn(o[n][2] * inv1, o[n][3] * inv1);
    }
}

// ---------------------------------------------------------------------------
// FP16 banded sliding-window attention (register P, exp2 softmax).
// ---------------------------------------------------------------------------
#define KBUFH (64 * ASTRH)
#define SWA_SMEM ((128 + 4 * 64) * ASTRH * 2)

__global__ void __launch_bounds__(256, 2) sw_attn_f16_kernel(
    const __half* __restrict__ q, const __half* __restrict__ kv,
    __half* __restrict__ out)
{
    extern __shared__ __half smh[];
    __half* Ps = smh;
    __half* Ks = smh + 128 * ASTRH;
    __half* Vs = Ks + 2 * KBUFH;

    const int tid = threadIdx.x;
    const int wid = tid >> 5;
    const int lane = tid & 31;
    const int b = blockIdx.y >> 3;
    const int h = blockIdx.y & 7;
    const int t0 = blockIdx.x * 128;
    const int wm = wid * 16;

#pragma unroll
    for (int i = 0; i < 4; ++i) {
        int idx = i * 256 + tid;
        int r = idx >> 3, c = (idx & 7) * 8;
        cp_async16(&Ps[r * ASTRH + c],
                   q + ((size_t)(t0 + r) * B_ + b) * D_ + h * 64 + c);
    }
    {
        int key0 = t0 - 16;
#pragma unroll
        for (int i = 0; i < 2; ++i) {
            int idx = i * 256 + tid;
            int r = idx >> 3, c = (idx & 7) * 8;
            int key = min(max(key0 + r, 0), S_ - 1);
            const __half* base = kv + ((size_t)key * B_ + b) * 1024 + h * 64;
            cp_async16(&Ks[r * ASTRH + c], base + c);
            cp_async16(&Vs[r * ASTRH + c], base + 512 + c);
        }
    }
    cp_commit();
    cp_wait0();
    __syncthreads();

    unsigned qf[4][4];
    {
        const __half2 sc2 = __float2half2_rn(SCALE_ * LOG2E_);
        const int qrow = wm + (lane & 15);
        const int qko = (lane >> 4) * 8;
#pragma unroll
        for (int ks = 0; ks < 4; ++ks) {
            unsigned r0, r1, r2, r3;
            ldsm_x4h(r0, r1, r2, r3, &Ps[qrow * ASTRH + ks * 16 + qko]);
            unsigned rr[4] = {r0, r1, r2, r3};
#pragma unroll
            for (int j = 0; j < 4; ++j) {
                __half2 v = *reinterpret_cast<__half2*>(&rr[j]);
                v = __hmul2(v, sc2);
                qf[ks][j] = *reinterpret_cast<unsigned*>(&v);
            }
        }
    }

    float o[8][4];
#pragma unroll
    for (int n = 0; n < 8; ++n)
#pragma unroll
        for (int c = 0; c < 4; ++c) o[n][c] = 0.f;
    float m0 = -1e30f, m1 = -1e30f, l0 = 0.f, l1 = 0.f;

    const int brow_base = (lane & 7) + ((lane >> 4) * 8);
    const int bko = ((lane >> 3) & 1) * 8;
    const int prow0 = wm + (lane >> 2);
    const int pcol = 2 * (lane & 3);
    const int v_row = lane & 15;
    const int v_coff = (lane >> 4) * 8;

    for (int kt = 0; kt < 3; ++kt) {
        const int buf = kt & 1;
        const int key0 = t0 - 16 + kt * 64;

        if (kt + 1 < 3) {
            int nk0 = t0 - 16 + (kt + 1) * 64;
            __half* kd = Ks + (buf ^ 1) * KBUFH;
            __half* vd = Vs + (buf ^ 1) * KBUFH;
#pragma unroll
            for (int i = 0; i < 2; ++i) {
                int idx = i * 256 + tid;
                int r = idx >> 3, c = (idx & 7) * 8;
                int key = min(max(nk0 + r, 0), S_ - 1);
                const __half* base = kv + ((size_t)key * B_ + b) * 1024 + h * 64;
                cp_async16(&kd[r * ASTRH + c], base + c);
                cp_async16(&vd[r * ASTRH + c], base + 512 + c);
            }
            cp_commit();
            cp_wait1();
        } else {
            cp_wait0();
        }
        __syncthreads();

        const __half* Kb = Ks + buf * KBUFH;
        float s[8][4];
#pragma unroll
        for (int n = 0; n < 8; ++n)
#pragma unroll
            for (int c = 0; c < 4; ++c) s[n][c] = 0.f;
#pragma unroll
        for (int ks = 0; ks < 4; ++ks) {
#pragma unroll
            for (int ng = 0; ng < 4; ++ng) {
                unsigned r0, r1, r2, r3;
                ldsm_x4h(r0, r1, r2, r3, &Kb[(brow_base + ng * 16) * ASTRH + ks * 16 + bko]);
                mma_f16(s[ng * 2][0], s[ng * 2][1], s[ng * 2][2], s[ng * 2][3],
                        qf[ks][0], qf[ks][1], qf[ks][2], qf[ks][3], r0, r1);
                mma_f16(s[ng * 2 + 1][0], s[ng * 2 + 1][1], s[ng * 2 + 1][2], s[ng * 2 + 1][3],
                        qf[ks][0], qf[ks][1], qf[ks][2], qf[ks][3], r2, r3);
            }
        }

#pragma unroll
        for (int n = 0; n < 8; ++n) {
#pragma unroll
            for (int c = 0; c < 4; ++c) {
                int key = key0 + n * 8 + pcol + (c & 1);
                int qg = t0 + prow0 + ((c >> 1) * 8);
                bool valid = (key >= 0) && (key < S_) && (key - qg <= W_) && (qg - key <= W_);
                if (!valid) s[n][c] = -1e38f;
            }
        }

        float mx0 = -1e30f, mx1 = -1e30f;
#pragma unroll
        for (int n = 0; n < 8; ++n) {
            mx0 = fmaxf(mx0, fmaxf(s[n][0], s[n][1]));
            mx1 = fmaxf(mx1, fmaxf(s[n][2], s[n][3]));
        }
        mx0 = fmaxf(mx0, __shfl_xor_sync(0xffffffffu, mx0, 1));
        mx0 = fmaxf(mx0, __shfl_xor_sync(0xffffffffu, mx0, 2));
        mx1 = fmaxf(mx1, __shfl_xor_sync(0xffffffffu, mx1, 1));
        mx1 = fmaxf(mx1, __shfl_xor_sync(0xffffffffu, mx1, 2));

        float mn0 = fmaxf(m0, mx0), mn1 = fmaxf(m1, mx1);
        float corr0 = exp2f(m0 - mn0), corr1 = exp2f(m1 - mn1);
        m0 = mn0; m1 = mn1;
        l0 *= corr0; l1 *= corr1;
#pragma unroll
        for (int n = 0; n < 8; ++n) {
            o[n][0] *= corr0; o[n][1] *= corr0;
            o[n][2] *= corr1; o[n][3] *= corr1;
        }

        unsigned pf[4][4];
#pragma unroll
        for (int j = 0; j < 4; ++j) {
            float p00 = exp2f(s[2 * j][0] - mn0);
            float p01 = exp2f(s[2 * j][1] - mn0);
            float p02 = exp2f(s[2 * j][2] - mn1);
            float p03 = exp2f(s[2 * j][3] - mn1);
            float p10 = exp2f(s[2 * j + 1][0] - mn0);
            float p11 = exp2f(s[2 * j + 1][1] - mn0);
            float p12 = exp2f(s[2 * j + 1][2] - mn1);
            float p13 = exp2f(s[2 * j + 1][3] - mn1);
            l0 += p00 + p01 + p10 + p11;
            l1 += p02 + p03 + p12 + p13;
            __half2 hh;
            hh = __floats2half2_rn(p00, p01); pf[j][0] = *reinterpret_cast<unsigned*>(&hh);
            hh = __floats2half2_rn(p02, p03); pf[j][1] = *reinterpret_cast<unsigned*>(&hh);
            hh = __floats2half2_rn(p10, p11); pf[j][2] = *reinterpret_cast<unsigned*>(&hh);
            hh = __floats2half2_rn(p12, p13); pf[j][3] = *reinterpret_cast<unsigned*>(&hh);
        }

        const __half* Vb = Vs + buf * KBUFH;
#pragma unroll
        for (int ks = 0; ks < 4; ++ks) {
#pragma unroll
            for (int ng = 0; ng < 4; ++ng) {
                unsigned r0, r1, r2, r3;
                ldsm_x4h_t(r0, r1, r2, r3,
                           &Vb[(ks * 16 + v_row) * ASTRH + ng * 16 + v_coff]);
                mma_f16(o[ng * 2][0], o[ng * 2][1], o[ng * 2][2], o[ng * 2][3],
                        pf[ks][0], pf[ks][1], pf[ks][2], pf[ks][3], r0, r1);
                mma_f16(o[ng * 2 + 1][0], o[ng * 2 + 1][1], o[ng * 2 + 1][2], o[ng * 2 + 1][3],
                        pf[ks][0], pf[ks][1], pf[ks][2], pf[ks][3], r2, r3);
            }
        }
        __syncthreads();
    }

    l0 += __shfl_xor_sync(0xffffffffu, l0, 1);
    l0 += __shfl_xor_sync(0xffffffffu, l0, 2);
    l1 += __shfl_xor_sync(0xffffffffu, l1, 1);
    l1 += __shfl_xor_sync(0xffffffffu, l1, 2);
    float inv0 = 1.f / l0, inv1 = 1.f / l1;

    __half* ob0 = out + ((size_t)(t0 + prow0) * B_ + b) * D_ + h * 64 + pcol;
    __half* ob1 = out + ((size_t)(t0 + prow0 + 8) * B_ + b) * D_ + h * 64 + pcol;
#pragma unroll
    for (int n = 0; n < 8; ++n) {
        *reinterpret_cast<__half2*>(ob0 + n * 8) = __floats2half2_rn(o[n][0] * inv0, o[n][1] * inv0);
        *reinterpret_cast<__half2*>(ob1 + n * 8) = __floats2half2_rn(o[n][2] * inv1, o[n][3] * inv1);
    }
}

// ---------------------------------------------------------------------------
// Warp-per-row fused residual-add(y fp16) + LayerNorm. 8 rows per block.
// Lane owns 16 elements as 4 coalesced float4 chunks. No smem, no bar.sync.
// ---------------------------------------------------------------------------
__global__ void __launch_bounds__(256) add_ln_h_kernel(
    const float* __restrict__ x, const __half* __restrict__ y,
    const float* __restrict__ g, const float* __restrict__ beta,
    float* __restrict__ out, __half* __restrict__ out16)
{
    const int row = blockIdx.x * 8 + (threadIdx.x >> 5);
    const int lane = threadIdx.x & 31;
    const size_t base = (size_t)row * D_;

    float v[4][4];
#pragma unroll
    for (int j = 0; j < 4; ++j) {
        int col = j * 128 + lane * 4;
        float4 xv = *reinterpret_cast<const float4*>(x + base + col);
        __half2 y0 = *reinterpret_cast<const __half2*>(y + base + col);
        __half2 y1 = *reinterpret_cast<const __half2*>(y + base + col + 2);
        float2 f0 = __half22float2(y0);
        float2 f1 = __half22float2(y1);
        v[j][0] = xv.x + f0.x;
        v[j][1] = xv.y + f0.y;
        v[j][2] = xv.z + f1.x;
        v[j][3] = xv.w + f1.y;
    }

    float s = 0.f, sq = 0.f;
#pragma unroll
    for (int j = 0; j < 4; ++j)
#pragma unroll
        for (int q = 0; q < 4; ++q) {
            s += v[j][q];
            sq += v[j][q] * v[j][q];
        }
#pragma unroll
    for (int o = 16; o > 0; o >>= 1) {
        s  += __shfl_xor_sync(0xffffffffu, s, o);
        sq += __shfl_xor_sync(0xffffffffu, sq, o);
    }
    float mean = s * (1.f / D_);
    float rstd = rsqrtf(sq * (1.f / D_) - mean * mean + EPS_);

#pragma unroll
    for (int j = 0; j < 4; ++j) {
        int col = j * 128 + lane * 4;
        float4 gv = *reinterpret_cast<const float4*>(g + col);
        float4 bv = *reinterpret_cast<const float4*>(beta + col);
        float r0 = (v[j][0] - mean) * rstd * gv.x + bv.x;
        float r1 = (v[j][1] - mean) * rstd * gv.y + bv.y;
        float r2 = (v[j][2] - mean) * rstd * gv.z + bv.z;
        float r3 = (v[j][3] - mean) * rstd * gv.w + bv.w;
        *reinterpret_cast<float4*>(out + base + col) = make_float4(r0, r1, r2, r3);
        if (out16) {
            *reinterpret_cast<__half2*>(out16 + base + col)     = __floats2half2_rn(r0, r1);
            *reinterpret_cast<__half2*>(out16 + base + col + 2) = __floats2half2_rn(r2, r3);
        }
    }
}

// ---------------------------------------------------------------------------
// Launch
// ---------------------------------------------------------------------------
extern "C" void kernel_launch(void* const* d_in, const int* in_sizes, int n_in,
                              void* d_out, int out_size)
{
    (void)in_sizes; (void)n_in; (void)out_size;
    const float* tgt        = (const float*)d_in[0];
    const float* memory     = (const float*)d_in[1];
    const float* in_proj_w  = (const float*)d_in[2];
    const float* in_proj_b  = (const float*)d_in[3];
    const float* out_proj_w = (const float*)d_in[4];
    const float* out_proj_b = (const float*)d_in[5];
    const float* sw_q_w = (const float*)d_in[6];
    const float* sw_q_b = (const float*)d_in[7];
    const float* sw_k_w = (const float*)d_in[8];
    const float* sw_k_b = (const float*)d_in[9];
    const float* sw_v_w = (const float*)d_in[10];
    const float* sw_v_b = (const float*)d_in[11];
    const float* sw_o_w = (const float*)d_in[12];
    const float* sw_o_b = (const float*)d_in[13];
    const float* lin1_w = (const float*)d_in[14];
    const float* lin1_b = (const float*)d_in[15];
    const float* lin2_w = (const float*)d_in[16];
    const float* lin2_b = (const float*)d_in[17];
    const float* n1_g = (const float*)d_in[18];
    const float* n1_b = (const float*)d_in[19];
    const float* n2_g = (const float*)d_in[20];
    const float* n2_b = (const float*)d_in[21];
    const float* n3_g = (const float*)d_in[22];
    const float* n3_b = (const float*)d_in[23];
    float* out = (float*)d_out;

    float* s = nullptr;
    cudaGetSymbolAddress((void**)&s, g_scratch);
    float* x1   = s + FOFF_X1;
    float* x2   = s + FOFF_X2;
    float* bcat = s + FOFF_BCAT;
    __half* hb = (__half*)(s + HALF_BASE_F);
    __half* qkv16    = hb + HOFF_QKV;
    __half* attn16   = hb + HOFF_ATTN;
    __half* swq16    = hb + HOFF_SWQ;
    __half* swkv16   = hb + HOFF_SWKV;
    __half* swattn16 = hb + HOFF_SWATTN;
    __half* hbuf16   = hb + HOFF_HBUF;
    __half* tgt16    = hb + HOFF_TGT;
    __half* mem16    = hb + HOFF_MEM;
    __half* x1h      = hb + HOFF_X1H;
    __half* x2h      = hb + HOFF_X2H;
    __half* w_in     = hb + HOFF_WIN;
    __half* w_out    = hb + HOFF_WOUT;
    __half* w_swq    = hb + HOFF_WSWQ;
    __half* w_swkv   = hb + HOFF_WSWKV;
    __half* w_swo    = hb + HOFF_WSWO;
    __half* w_lin1   = hb + HOFF_WLIN1;
    __half* w_lin2   = hb + HOFF_WLIN2;
    __half* proj16   = hb + HOFF_PROJ16;
    __half* ff16     = hb + HOFF_FF16;

    cudaFuncSetAttribute(self_attn_f16_kernel,
                         cudaFuncAttributeMaxDynamicSharedMemorySize, ATTN_SMEM);
    cudaFuncSetAttribute(sw_attn_f16_kernel,
                         cudaFuncAttributeMaxDynamicSharedMemorySize, SWA_SMEM);
    cudaFuncSetAttribute(gemm_f16_kernel,
                         cudaFuncAttributeMaxDynamicSharedMemorySize, G128_SMEM);
    cudaFuncSetAttribute(gemm_f16_dual_kernel,
                         cudaFuncAttributeMaxDynamicSharedMemorySize, G128_SMEM);
    cudaFuncSetAttribute(gemm_f16_n64_kernel,
                         cudaFuncAttributeMaxDynamicSharedMemorySize, G64_SMEM);

    // one fused convert (incl. KV weight concat + bias concat)
    f2h_multi_kernel<<<8192, 256>>>(tgt, tgt16, memory, mem16,
                                    in_proj_w, w_in, out_proj_w, w_out,
                                    sw_q_w, w_swq, sw_o_w, w_swo,
                                    lin1_w, w_lin1, lin2_w, w_lin2,
                                    sw_k_w, w_swkv, sw_v_w, w_swkv + 262144,
                                    sw_k_b, sw_v_b, bcat);

    // combined QKV (N=1536, 12 blocks) + fused KV (N=1024, 8 blocks)
    gemm_f16_dual_kernel<<<dim3(20, 32), 256, G128_SMEM>>>(
        tgt16, w_in, in_proj_b, qkv16, 3 * D_,
        mem16, w_swkv, bcat, swkv16, 1024,
        D_, 12);
    // self attention
    self_attn_f16_kernel<<<dim3(8, 32), 256, ATTN_SMEM>>>(qkv16, attn16);
    // out projection -> fp16
    gemm_f16_n64_kernel<<<dim3(8, 32), 256, G64_SMEM>>>(attn16, w_out, out_proj_b, proj16,
                                                        NROWS, D_, D_, 0, 1);
    // add + LN1 (warp-per-row)
    add_ln_h_kernel<<<NROWS / 8, 256>>>(tgt, proj16, n1_g, n1_b, x1, x1h);
    // sw q projection
    gemm_f16_n64_kernel<<<dim3(8, 32), 256, G64_SMEM>>>(x1h, w_swq, sw_q_b, swq16,
                                                        NROWS, D_, D_, 0, 1);
    // banded attention
    sw_attn_f16_kernel<<<dim3(8, 32), 256, SWA_SMEM>>>(swq16, swkv16, swattn16);
    // sw out projection -> fp16
    gemm_f16_n64_kernel<<<dim3(8, 32), 256, G64_SMEM>>>(swattn16, w_swo, sw_o_b, proj16,
                                                        NROWS, D_, D_, 0, 1);
    // add + LN2
    add_ln_h_kernel<<<NROWS / 8, 256>>>(x1, proj16, n2_g, n2_b, x2, x2h);
    // FFN up + ReLU
    gemm_f16_kernel<<<dim3(16, 32), 256, G128_SMEM>>>(x2h, w_lin1, lin1_b, hbuf16,
                                                      NROWS, DFF_, D_, 1, 1);
    // FFN down -> fp16
    gemm_f16_n64_kernel<<<dim3(8, 32), 256, G64_SMEM>>>(hbuf16, w_lin2, lin2_b, ff16,
                                                        NROWS, D_, DFF_, 0, 1);
    // add + LN3 -> output (fp32 only)
    add_ln_h_kernel<<<NROWS / 8, 256>>>(x2, ff16, n3_g, n3_b, out, nullptr);
}

// round 16
// speedup vs baseline: 1.0469x; 1.0155x over previous
#include <cuda_runtime.h>
#include <cuda_fp16.h>
#include <stdint.h>
#include <math.h>

#define T_ 1024
#define S_ 1024
#define B_ 4
#define D_ 512
#define H_ 8
#define HD_ 64
#define DFF_ 2048
#define W_ 16
#define NROWS (T_ * B_)
#define SCALE_ 0.125f
#define LOG2E_ 1.4426950408889634f
#define EPS_ 1e-5f

// fp32 region (float offsets)
#define FOFF_X1     0
#define FOFF_X2     2097152
#define FOFF_BCAT   4194304
#define HALF_BASE_F 5000000

// half region (half offsets)
#define HOFF_QKV    0
#define HOFF_ATTN   6291456
#define HOFF_SWQ    8388608
#define HOFF_SWKV   10485760
#define HOFF_SWATTN 14680064
#define HOFF_HBUF   16777216
#define HOFF_TGT    25165824
#define HOFF_MEM    27262976
#define HOFF_X1H    29360128
#define HOFF_X2H    31457280
#define HOFF_WIN    33554432
#define HOFF_WOUT   34340864
#define HOFF_WSWQ   34603008
#define HOFF_WSWKV  34865152
#define HOFF_WSWO   35389440
#define HOFF_WLIN1  35651584
#define HOFF_WLIN2  36700160
#define HOFF_PROJ16 37748736
#define HOFF_FF16   39845888

#define SCRATCH_FLOATS 33554432
__device__ float g_scratch[SCRATCH_FLOATS];

// ---------------------------------------------------------------------------
// PTX helpers
// ---------------------------------------------------------------------------
__device__ __forceinline__ void cp_async16(void* smem_ptr, const void* gmem_ptr) {
    unsigned saddr = (unsigned)__cvta_generic_to_shared(smem_ptr);
    asm volatile("cp.async.cg.shared.global [%0], [%1], 16;\n"
                 :: "r"(saddr), "l"(gmem_ptr));
}
__device__ __forceinline__ void cp_commit() {
    asm volatile("cp.async.commit_group;\n");
}
__device__ __forceinline__ void cp_wait0() {
    asm volatile("cp.async.wait_group 0;\n");
}
__device__ __forceinline__ void cp_wait1() {
    asm volatile("cp.async.wait_group 1;\n");
}
__device__ __forceinline__ void ldsm_x4h(unsigned& r0, unsigned& r1, unsigned& r2, unsigned& r3,
                                         const __half* p) {
    unsigned saddr = (unsigned)__cvta_generic_to_shared((void*)p);
    asm volatile("ldmatrix.sync.aligned.m8n8.x4.shared.b16 {%0,%1,%2,%3}, [%4];\n"
                 : "=r"(r0), "=r"(r1), "=r"(r2), "=r"(r3) : "r"(saddr));
}
__device__ __forceinline__ void ldsm_x4h_t(unsigned& r0, unsigned& r1, unsigned& r2, unsigned& r3,
                                           const __half* p) {
    unsigned saddr = (unsigned)__cvta_generic_to_shared((void*)p);
    asm volatile("ldmatrix.sync.aligned.m8n8.x4.trans.shared.b16 {%0,%1,%2,%3}, [%4];\n"
                 : "=r"(r0), "=r"(r1), "=r"(r2), "=r"(r3) : "r"(saddr));
}
__device__ __forceinline__ void mma_f16(float& c0, float& c1, float& c2, float& c3,
                                        unsigned a0, unsigned a1, unsigned a2, unsigned a3,
                                        unsigned b0, unsigned b1) {
    asm volatile("mma.sync.aligned.m16n8k16.row.col.f32.f16.f16.f32 "
                 "{%0,%1,%2,%3}, {%4,%5,%6,%7}, {%8,%9}, {%0,%1,%2,%3};\n"
                 : "+f"(c0), "+f"(c1), "+f"(c2), "+f"(c3)
                 : "r"(a0), "r"(a1), "r"(a2), "r"(a3), "r"(b0), "r"(b1));
}

// ---------------------------------------------------------------------------
// fp32->fp16 fused convert: 10 segments incl. KV weight concat + bias copy.
// ---------------------------------------------------------------------------
__global__ void __launch_bounds__(256) f2h_multi_kernel(
    const float* __restrict__ s0, __half* __restrict__ d0,
    const float* __restrict__ s1, __half* __restrict__ d1,
    const float* __restrict__ s2, __half* __restrict__ d2,
    const float* __restrict__ s3, __half* __restrict__ d3,
    const float* __restrict__ s4, __half* __restrict__ d4,
    const float* __restrict__ s5, __half* __restrict__ d5,
    const float* __restrict__ s6, __half* __restrict__ d6,
    const float* __restrict__ s7, __half* __restrict__ d7,
    const float* __restrict__ s8, __half* __restrict__ d8,
    const float* __restrict__ s9, __half* __restrict__ d9,
    const float* __restrict__ kb, const float* __restrict__ vb,
    float* __restrict__ bcat)
{
    if (blockIdx.x == 0) {
        int t = threadIdx.x;
        bcat[t] = kb[t];          bcat[512 + t] = vb[t];
        bcat[256 + t] = kb[256 + t]; bcat[768 + t] = vb[256 + t];
    }
    int idx = (blockIdx.x * 256 + threadIdx.x) * 4;
    const float* src; __half* dst; int off;
    if      (idx < 2097152) { src = s0; dst = d0; off = idx; }
    else if (idx < 4194304) { src = s1; dst = d1; off = idx - 2097152; }
    else if (idx < 4980736) { src = s2; dst = d2; off = idx - 4194304; }
    else if (idx < 5242880) { src = s3; dst = d3; off = idx - 4980736; }
    else if (idx < 5505024) { src = s4; dst = d4; off = idx - 5242880; }
    else if (idx < 5767168) { src = s5; dst = d5; off = idx - 5505024; }
    else if (idx < 6815744) { src = s6; dst = d6; off = idx - 5767168; }
    else if (idx < 7864320) { src = s7; dst = d7; off = idx - 6815744; }
    else if (idx < 8126464) { src = s8; dst = d8; off = idx - 7864320; }
    else                    { src = s9; dst = d9; off = idx - 8126464; }
    float4 v = *reinterpret_cast<const float4*>(src + off);
    *reinterpret_cast<__half2*>(dst + off)     = __floats2half2_rn(v.x, v.y);
    *reinterpret_cast<__half2*>(dst + off + 2) = __floats2half2_rn(v.z, v.w);
}

// ---------------------------------------------------------------------------
// FP16 GEMM 128x128 core, BK=64, 3-stage pipeline.
// ---------------------------------------------------------------------------
#define STR64 72
#define ASTG (128 * STR64)
#define G128_SMEM (6 * ASTG * 2)

__device__ __forceinline__ void gemm128_body(
    const __half* __restrict__ A, const __half* __restrict__ Wt,
    const float* __restrict__ bias, void* __restrict__ Cout,
    int N, int K, int relu, int out16, int m0, int n0, __half* sg)
{
    __half* As = sg;
    __half* Bs = sg + 3 * ASTG;

    const int tid  = threadIdx.x;
    const int wid  = tid >> 5;
    const int lane = tid & 31;
    const int wm   = (wid & 3) * 32;
    const int wn   = (wid >> 2) * 64;

    float acc[2][8][4];
#pragma unroll
    for (int i = 0; i < 2; ++i)
#pragma unroll
        for (int j = 0; j < 8; ++j)
#pragma unroll
            for (int q = 0; q < 4; ++q) acc[i][j][q] = 0.f;

    const int ntiles = K / 64;
    const __half* Abase = A + (size_t)m0 * K;
    const __half* Bbase = Wt + (size_t)n0 * K;

    auto load_stage = [&](int t, int st) {
        int k0 = t * 64;
        __half* Ad = As + st * ASTG;
        __half* Bd = Bs + st * ASTG;
#pragma unroll
        for (int it = 0; it < 4; ++it) {
            int idx = it * 256 + tid;
            int row = idx >> 3, col = (idx & 7) * 8;
            cp_async16(&Ad[row * STR64 + col], Abase + (size_t)row * K + k0 + col);
            cp_async16(&Bd[row * STR64 + col], Bbase + (size_t)row * K + k0 + col);
        }
    };

    load_stage(0, 0); cp_commit();
    load_stage(1, 1); cp_commit();

    const int a_row = wm + (lane & 15);
    const int a_koff = (lane >> 4) * 8;
    const int b_row_base = wn + (lane & 7) + ((lane >> 4) * 8);
    const int b_koff = ((lane >> 3) & 1) * 8;

    for (int t = 0; t < ntiles; ++t) {
        cp_wait1();
        __syncthreads();

        int ps = t + 2;
        if (ps < ntiles) load_stage(ps, ps % 3);
        cp_commit();

        const int buf = t % 3;
        const __half* Ab = As + buf * ASTG;
        const __half* Bb = Bs + buf * ASTG;
#pragma unroll
        for (int ks = 0; ks < 4; ++ks) {
            unsigned a[2][4];
            unsigned b[8][2];
#pragma unroll
            for (int im = 0; im < 2; ++im)
                ldsm_x4h(a[im][0], a[im][1], a[im][2], a[im][3],
                         &Ab[(a_row + im * 16) * STR64 + ks * 16 + a_koff]);
#pragma unroll
            for (int ng = 0; ng < 4; ++ng) {
                unsigned r0, r1, r2, r3;
                ldsm_x4h(r0, r1, r2, r3,
                         &Bb[(b_row_base + ng * 16) * STR64 + ks * 16 + b_koff]);
                b[ng * 2][0] = r0; b[ng * 2][1] = r1;
                b[ng * 2 + 1][0] = r2; b[ng * 2 + 1][1] = r3;
            }
#pragma unroll
            for (int im = 0; im < 2; ++im)
#pragma unroll
                for (int in = 0; in < 8; ++in)
                    mma_f16(acc[im][in][0], acc[im][in][1], acc[im][in][2], acc[im][in][3],
                            a[im][0], a[im][1], a[im][2], a[im][3],
                            b[in][0], b[in][1]);
        }
    }

    const int row_base = m0 + wm + (lane >> 2);
    const int col_base = n0 + wn + (lane & 3) * 2;
#pragma unroll
    for (int im = 0; im < 2; ++im) {
#pragma unroll
        for (int in = 0; in < 8; ++in) {
            int col = col_base + in * 8;
            float b0 = bias[col], b1 = bias[col + 1];
            int r0 = row_base + im * 16;
            float v0 = acc[im][in][0] + b0;
            float v1 = acc[im][in][1] + b1;
            float v2 = acc[im][in][2] + b0;
            float v3 = acc[im][in][3] + b1;
            if (relu) {
                v0 = fmaxf(v0, 0.f); v1 = fmaxf(v1, 0.f);
                v2 = fmaxf(v2, 0.f); v3 = fmaxf(v3, 0.f);
            }
            if (out16) {
                __half* C = (__half*)Cout;
                *reinterpret_cast<__half2*>(&C[(size_t)r0 * N + col]) = __floats2half2_rn(v0, v1);
                *reinterpret_cast<__half2*>(&C[(size_t)(r0 + 8) * N + col]) = __floats2half2_rn(v2, v3);
            } else {
                float* C = (float*)Cout;
                C[(size_t)r0 * N + col] = v0;
                C[(size_t)r0 * N + col + 1] = v1;
                C[(size_t)(r0 + 8) * N + col] = v2;
                C[(size_t)(r0 + 8) * N + col + 1] = v3;
            }
        }
    }
}

__global__ void __launch_bounds__(256, 2) gemm_f16_kernel(
    const __half* __restrict__ A, const __half* __restrict__ Wt,
    const float* __restrict__ bias, void* __restrict__ Cout,
    int M, int N, int K, int relu, int out16)
{
    extern __shared__ __half sg[];
    gemm128_body(A, Wt, bias, Cout, N, K, relu, out16,
                 blockIdx.y * 128, blockIdx.x * 128, sg);
}

__global__ void __launch_bounds__(256, 2) gemm_f16_dual_kernel(
    const __half* __restrict__ A1, const __half* __restrict__ W1,
    const float* __restrict__ b1, void* __restrict__ C1, int N1,
    const __half* __restrict__ A2, const __half* __restrict__ W2,
    const float* __restrict__ b2, void* __restrict__ C2, int N2,
    int K, int split)
{
    extern __shared__ __half sg[];
    if ((int)blockIdx.x < split)
        gemm128_body(A1, W1, b1, C1, N1, K, 0, 1,
                     blockIdx.y * 128, blockIdx.x * 128, sg);
    else
        gemm128_body(A2, W2, b2, C2, N2, K, 0, 1,
                     blockIdx.y * 128, (blockIdx.x - split) * 128, sg);
}

// ---------------------------------------------------------------------------
// FP16 GEMM 128x64, BK=128, 2-stage double buffer.
// smem halfs: As[2][128*136] | Bs[2][64*136]  (104448 B)
// ---------------------------------------------------------------------------
#define STR128 136
#define ASTG128 (128 * STR128)
#define BSTG128 (64 * STR128)
#define G64_SMEM ((2 * ASTG128 + 2 * BSTG128) * 2)

__global__ void __launch_bounds__(256, 2) gemm_f16_n64_kernel(
    const __half* __restrict__ A, const __half* __restrict__ Wt,
    const float* __restrict__ bias, void* __restrict__ Cout,
    int M, int N, int K, int relu, int out16)
{
    extern __shared__ __half sg[];
    __half* As = sg;
    __half* Bs = sg + 2 * ASTG128;

    const int tid  = threadIdx.x;
    const int wid  = tid >> 5;
    const int lane = tid & 31;
    const int wm   = (wid & 3) * 32;
    const int wn   = (wid >> 2) * 32;
    const int m0   = blockIdx.y * 128;
    const int n0   = blockIdx.x * 64;

    float acc[2][4][4];
#pragma unroll
    for (int i = 0; i < 2; ++i)
#pragma unroll
        for (int j = 0; j < 4; ++j)
#pragma unroll
            for (int q = 0; q < 4; ++q) acc[i][j][q] = 0.f;

    const int ntiles = K / 128;
    const __half* Abase = A + (size_t)m0 * K;
    const __half* Bbase = Wt + (size_t)n0 * K;

    // stage loader: A 128x128 halfs (8 it), B 64x128 halfs (4 it)
    auto load_stage = [&](int t, int st) {
        int k0 = t * 128;
        __half* Ad = As + st * ASTG128;
        __half* Bd = Bs + st * BSTG128;
#pragma unroll
        for (int it = 0; it < 8; ++it) {
            int idx = it * 256 + tid;
            int row = idx >> 4, col = (idx & 15) * 8;
            cp_async16(&Ad[row * STR128 + col], Abase + (size_t)row * K + k0 + col);
        }
#pragma unroll
        for (int it = 0; it < 4; ++it) {
            int idx = it * 256 + tid;
            int row = idx >> 4, col = (idx & 15) * 8;
            cp_async16(&Bd[row * STR128 + col], Bbase + (size_t)row * K + k0 + col);
        }
    };

    load_stage(0, 0); cp_commit();

    const int a_row = wm + (lane & 15);
    const int a_koff = (lane >> 4) * 8;
    const int b_row_base = wn + (lane & 7) + ((lane >> 4) * 8);
    const int b_koff = ((lane >> 3) & 1) * 8;

    for (int t = 0; t < ntiles; ++t) {
        cp_wait0();            // stage t complete
        __syncthreads();       // all threads done computing t-1 (protects buf (t+1)&1)

        if (t + 1 < ntiles) {
            load_stage(t + 1, (t + 1) & 1);
            cp_commit();
        }

        const int buf = t & 1;
        const __half* Ab = As + buf * ASTG128;
        const __half* Bb = Bs + buf * BSTG128;
#pragma unroll
        for (int ks = 0; ks < 8; ++ks) {
            unsigned a[2][4];
            unsigned b[4][2];
#pragma unroll
            for (int im = 0; im < 2; ++im)
                ldsm_x4h(a[im][0], a[im][1], a[im][2], a[im][3],
                         &Ab[(a_row + im * 16) * STR128 + ks * 16 + a_koff]);
#pragma unroll
            for (int ng = 0; ng < 2; ++ng) {
                unsigned r0, r1, r2, r3;
                ldsm_x4h(r0, r1, r2, r3,
                         &Bb[(b_row_base + ng * 16) * STR128 + ks * 16 + b_koff]);
                b[ng * 2][0] = r0; b[ng * 2][1] = r1;
                b[ng * 2 + 1][0] = r2; b[ng * 2 + 1][1] = r3;
            }
#pragma unroll
            for (int im = 0; im < 2; ++im)
#pragma unroll
                for (int in = 0; in < 4; ++in)
                    mma_f16(acc[im][in][0], acc[im][in][1], acc[im][in][2], acc[im][in][3],
                            a[im][0], a[im][1], a[im][2], a[im][3],
                            b[in][0], b[in][1]);
        }
    }

    const int row_base = m0 + wm + (lane >> 2);
    const int col_base = n0 + wn + (lane & 3) * 2;
#pragma unroll
    for (int im = 0; im < 2; ++im) {
#pragma unroll
        for (int in = 0; in < 4; ++in) {
            int col = col_base + in * 8;
            float b0 = bias[col], b1 = bias[col + 1];
            int r0 = row_base + im * 16;
            float v0 = acc[im][in][0] + b0;
            float v1 = acc[im][in][1] + b1;
            float v2 = acc[im][in][2] + b0;
            float v3 = acc[im][in][3] + b1;
            if (relu) {
                v0 = fmaxf(v0, 0.f); v1 = fmaxf(v1, 0.f);
                v2 = fmaxf(v2, 0.f); v3 = fmaxf(v3, 0.f);
            }
            if (out16) {
                __half* C = (__half*)Cout;
                *reinterpret_cast<__half2*>(&C[(size_t)r0 * N + col]) = __floats2half2_rn(v0, v1);
                *reinterpret_cast<__half2*>(&C[(size_t)(r0 + 8) * N + col]) = __floats2half2_rn(v2, v3);
            } else {
                float* C = (float*)Cout;
                C[(size_t)r0 * N + col] = v0;
                C[(size_t)r0 * N + col + 1] = v1;
                C[(size_t)(r0 + 8) * N + col] = v2;
                C[(size_t)(r0 + 8) * N + col + 1] = v3;
            }
        }
    }
}

// ---------------------------------------------------------------------------
// FP16 flash self-attention: 128-key tiles, register P, exp2 softmax.
// ---------------------------------------------------------------------------
#define ASTRH 72
#define KB128 (128 * ASTRH)
#define ROWH 6144
#define ATTN_SMEM ((128 + 4 * 128) * ASTRH * 2)

__global__ void __launch_bounds__(256, 2) self_attn_f16_kernel(
    const __half* __restrict__ qkv, __half* __restrict__ out)
{
    extern __shared__ __half smh[];
    __half* Ps = smh;
    __half* Ks = smh + 128 * ASTRH;
    __half* Vs = Ks + 2 * KB128;

    const int tid = threadIdx.x;
    const int wid = tid >> 5;
    const int lane = tid & 31;
    const int b = blockIdx.y >> 3;
    const int h = blockIdx.y & 7;
    const int t0 = blockIdx.x * 128;
    const int wm = wid * 16;

    const __half* qbase = qkv + ((size_t)t0 * B_ + b) * 1536 + h * 64;
    const __half* kroot = qkv + (size_t)b * 1536 + 512 + h * 64;
    const __half* vroot = qkv + (size_t)b * 1536 + 1024 + h * 64;

#pragma unroll
    for (int i = 0; i < 4; ++i) {
        int idx = i * 256 + tid;
        int r = idx >> 3, c = (idx & 7) * 8;
        cp_async16(&Ps[r * ASTRH + c], qbase + (size_t)r * ROWH + c);
    }
#pragma unroll
    for (int i = 0; i < 4; ++i) {
        int idx = i * 256 + tid;
        int r = idx >> 3, c = (idx & 7) * 8;
        cp_async16(&Ks[r * ASTRH + c], kroot + (size_t)r * ROWH + c);
        cp_async16(&Vs[r * ASTRH + c], vroot + (size_t)r * ROWH + c);
    }
    cp_commit();
    cp_wait0();
    __syncthreads();

    unsigned qf[4][4];
    {
        const __half2 sc2 = __float2half2_rn(SCALE_ * LOG2E_);
        const int qrow = wm + (lane & 15);
        const int qko = (lane >> 4) * 8;
#pragma unroll
        for (int ks = 0; ks < 4; ++ks) {
            unsigned r0, r1, r2, r3;
            ldsm_x4h(r0, r1, r2, r3, &Ps[qrow * ASTRH + ks * 16 + qko]);
            unsigned rr[4] = {r0, r1, r2, r3};
#pragma unroll
            for (int j = 0; j < 4; ++j) {
                __half2 v = *reinterpret_cast<__half2*>(&rr[j]);
                v = __hmul2(v, sc2);
                qf[ks][j] = *reinterpret_cast<unsigned*>(&v);
            }
        }
    }

    float o[8][4];
#pragma unroll
    for (int n = 0; n < 8; ++n)
#pragma unroll
        for (int c = 0; c < 4; ++c) o[n][c] = 0.f;
    float m0 = -1e30f, m1 = -1e30f, l0 = 0.f, l1 = 0.f;

    const int brow_base = (lane & 7) + ((lane >> 4) * 8);
    const int bko = ((lane >> 3) & 1) * 8;
    const int prow0 = wm + (lane >> 2);
    const int pcol = 2 * (lane & 3);
    const int v_row = lane & 15;
    const int v_coff = (lane >> 4) * 8;

    for (int kt = 0; kt < 8; ++kt) {
        const int buf = kt & 1;

        if (kt + 1 < 8) {
            const __half* kb = kroot + (size_t)(kt + 1) * 128 * ROWH;
            const __half* vb = vroot + (size_t)(kt + 1) * 128 * ROWH;
            __half* kd = Ks + (buf ^ 1) * KB128;
            __half* vd = Vs + (buf ^ 1) * KB128;
#pragma unroll
            for (int i = 0; i < 4; ++i) {
                int idx = i * 256 + tid;
                int r = idx >> 3, c = (idx & 7) * 8;
                cp_async16(&kd[r * ASTRH + c], kb + (size_t)r * ROWH + c);
                cp_async16(&vd[r * ASTRH + c], vb + (size_t)r * ROWH + c);
            }
            cp_commit();
            cp_wait1();
        } else {
            cp_wait0();
        }
        __syncthreads();

#pragma unroll
        for (int half = 0; half < 2; ++half) {
            const __half* Kb = Ks + buf * KB128 + half * 64 * ASTRH;
            const __half* Vb = Vs + buf * KB128 + half * 64 * ASTRH;

            float s[8][4];
#pragma unroll
            for (int n = 0; n < 8; ++n)
#pragma unroll
                for (int c = 0; c < 4; ++c) s[n][c] = 0.f;
#pragma unroll
            for (int ks = 0; ks < 4; ++ks) {
#pragma unroll
                for (int ng = 0; ng < 4; ++ng) {
                    unsigned r0, r1, r2, r3;
                    ldsm_x4h(r0, r1, r2, r3, &Kb[(brow_base + ng * 16) * ASTRH + ks * 16 + bko]);
                    mma_f16(s[ng * 2][0], s[ng * 2][1], s[ng * 2][2], s[ng * 2][3],
                            qf[ks][0], qf[ks][1], qf[ks][2], qf[ks][3], r0, r1);
                    mma_f16(s[ng * 2 + 1][0], s[ng * 2 + 1][1], s[ng * 2 + 1][2], s[ng * 2 + 1][3],
                            qf[ks][0], qf[ks][1], qf[ks][2], qf[ks][3], r2, r3);
                }
            }

            float mx0 = -1e30f, mx1 = -1e30f;
#pragma unroll
            for (int n = 0; n < 8; ++n) {
                mx0 = fmaxf(mx0, fmaxf(s[n][0], s[n][1]));
                mx1 = fmaxf(mx1, fmaxf(s[n][2], s[n][3]));
            }
            mx0 = fmaxf(mx0, __shfl_xor_sync(0xffffffffu, mx0, 1));
            mx0 = fmaxf(mx0, __shfl_xor_sync(0xffffffffu, mx0, 2));
            mx1 = fmaxf(mx1, __shfl_xor_sync(0xffffffffu, mx1, 1));
            mx1 = fmaxf(mx1, __shfl_xor_sync(0xffffffffu, mx1, 2));

            float mn0 = fmaxf(m0, mx0), mn1 = fmaxf(m1, mx1);
            float corr0 = exp2f(m0 - mn0), corr1 = exp2f(m1 - mn1);
            m0 = mn0; m1 = mn1;
            l0 *= corr0; l1 *= corr1;
#pragma unroll
            for (int n = 0; n < 8; ++n) {
                o[n][0] *= corr0; o[n][1] *= corr0;
                o[n][2] *= corr1; o[n][3] *= corr1;
            }

            unsigned pf[4][4];
#pragma unroll
            for (int j = 0; j < 4; ++j) {
                float p00 = exp2f(s[2 * j][0] - mn0);
                float p01 = exp2f(s[2 * j][1] - mn0);
                float p02 = exp2f(s[2 * j][2] - mn1);
                float p03 = exp2f(s[2 * j][3] - mn1);
                float p10 = exp2f(s[2 * j + 1][0] - mn0);
                float p11 = exp2f(s[2 * j + 1][1] - mn0);
                float p12 = exp2f(s[2 * j + 1][2] - mn1);
                float p13 = exp2f(s[2 * j + 1][3] - mn1);
                l0 += p00 + p01 + p10 + p11;
                l1 += p02 + p03 + p12 + p13;
                __half2 hh;
                hh = __floats2half2_rn(p00, p01); pf[j][0] = *reinterpret_cast<unsigned*>(&hh);
                hh = __floats2half2_rn(p02, p03); pf[j][1] = *reinterpret_cast<unsigned*>(&hh);
                hh = __floats2half2_rn(p10, p11); pf[j][2] = *reinterpret_cast<unsigned*>(&hh);
                hh = __floats2half2_rn(p12, p13); pf[j][3] = *reinterpret_cast<unsigned*>(&hh);
            }

#pragma unroll
            for (int ks = 0; ks < 4; ++ks) {
#pragma unroll
                for (int ng = 0; ng < 4; ++ng) {
                    unsigned r0, r1, r2, r3;
                    ldsm_x4h_t(r0, r1, r2, r3,
                               &Vb[(ks * 16 + v_row) * ASTRH + ng * 16 + v_coff]);
                    mma_f16(o[ng * 2][0], o[ng * 2][1], o[ng * 2][2], o[ng * 2][3],
                            pf[ks][0], pf[ks][1], pf[ks][2], pf[ks][3], r0, r1);
                    mma_f16(o[ng * 2 + 1][0], o[ng * 2 + 1][1], o[ng * 2 + 1][2], o[ng * 2 + 1][3],
                            pf[ks][0], pf[ks][1], pf[ks][2], pf[ks][3], r2, r3);
                }
            }
        }
        __syncthreads();
    }

    l0 += __shfl_xor_sync(0xffffffffu, l0, 1);
    l0 += __shfl_xor_sync(0xffffffffu, l0, 2);
    l1 += __shfl_xor_sync(0xffffffffu, l1, 1);
    l1 += __shfl_xor_sync(0xffffffffu, l1, 2);
    float inv0 = 1.f / l0, inv1 = 1.f / l1;

    __half* ob0 = out + ((size_t)(t0 + prow0) * B_ + b) * D_ + h * 64 + pcol;
    __half* ob1 = out + ((size_t)(t0 + prow0 + 8) * B_ + b) * D_ + h * 64 + pcol;
#pragma unroll
    for (int n = 0; n < 8; ++n) {
        *reinterpret_cast<__half2*>(ob0 + n * 8) = __floats2half2_rn(o[n][0] * inv0, o[n][1] * inv0);
        *reinterpret_cast<__half2*>(ob1 + n * 8) = __floats2half2_rn(o[n][2] * inv1, o[n][3] * inv1);
    }
}

// ---------------------------------------------------------------------------
// FP16 banded sliding-window attention (register P, exp2 softmax).
// ---------------------------------------------------------------------------
#define KBUFH (64 * ASTRH)
#define SWA_SMEM ((128 + 4 * 64) * ASTRH * 2)

__global__ void __launch_bounds__(256, 2) sw_attn_f16_kernel(
    const __half* __restrict__ q, const __half* __restrict__ kv,
    __half* __restrict__ out)
{
    extern __shared__ __half smh[];
    __half* Ps = smh;
    __half* Ks = smh + 128 * ASTRH;
    __half* Vs = Ks + 2 * KBUFH;

    const int tid = threadIdx.x;
    const int wid = tid >> 5;
    const int lane = tid & 31;
    const int b = blockIdx.y >> 3;
    const int h = blockIdx.y & 7;
    const int t0 = blockIdx.x * 128;
    const int wm = wid * 16;

#pragma unroll
    for (int i = 0; i < 4; ++i) {
        int idx = i * 256 + tid;
        int r = idx >> 3, c = (idx & 7) * 8;
        cp_async16(&Ps[r * ASTRH + c],
                   q + ((size_t)(t0 + r) * B_ + b) * D_ + h * 64 + c);
    }
    {
        int key0 = t0 - 16;
#pragma unroll
        for (int i = 0; i < 2; ++i) {
            int idx = i * 256 + tid;
            int r = idx >> 3, c = (idx & 7) * 8;
            int key = min(max(key0 + r, 0), S_ - 1);
            const __half* base = kv + ((size_t)key * B_ + b) * 1024 + h * 64;
            cp_async16(&Ks[r * ASTRH + c], base + c);
            cp_async16(&Vs[r * ASTRH + c], base + 512 + c);
        }
    }
    cp_commit();
    cp_wait0();
    __syncthreads();

    unsigned qf[4][4];
    {
        const __half2 sc2 = __float2half2_rn(SCALE_ * LOG2E_);
        const int qrow = wm + (lane & 15);
        const int qko = (lane >> 4) * 8;
#pragma unroll
        for (int ks = 0; ks < 4; ++ks) {
            unsigned r0, r1, r2, r3;
            ldsm_x4h(r0, r1, r2, r3, &Ps[qrow * ASTRH + ks * 16 + qko]);
            unsigned rr[4] = {r0, r1, r2, r3};
#pragma unroll
            for (int j = 0; j < 4; ++j) {
                __half2 v = *reinterpret_cast<__half2*>(&rr[j]);
                v = __hmul2(v, sc2);
                qf[ks][j] = *reinterpret_cast<unsigned*>(&v);
            }
        }
    }

    float o[8][4];
#pragma unroll
    for (int n = 0; n < 8; ++n)
#pragma unroll
        for (int c = 0; c < 4; ++c) o[n][c] = 0.f;
    float m0 = -1e30f, m1 = -1e30f, l0 = 0.f, l1 = 0.f;

    const int brow_base = (lane & 7) + ((lane >> 4) * 8);
    const int bko = ((lane >> 3) & 1) * 8;
    const int prow0 = wm + (lane >> 2);
    const int pcol = 2 * (lane & 3);
    const int v_row = lane & 15;
    const int v_coff = (lane >> 4) * 8;

    for (int kt = 0; kt < 3; ++kt) {
        const int buf = kt & 1;
        const int key0 = t0 - 16 + kt * 64;

        if (kt + 1 < 3) {
            int nk0 = t0 - 16 + (kt + 1) * 64;
            __half* kd = Ks + (buf ^ 1) * KBUFH;
            __half* vd = Vs + (buf ^ 1) * KBUFH;
#pragma unroll
            for (int i = 0; i < 2; ++i) {
                int idx = i * 256 + tid;
                int r = idx >> 3, c = (idx & 7) * 8;
                int key = min(max(nk0 + r, 0), S_ - 1);
                const __half* base = kv + ((size_t)key * B_ + b) * 1024 + h * 64;
                cp_async16(&kd[r * ASTRH + c], base + c);
                cp_async16(&vd[r * ASTRH + c], base + 512 + c);
            }
            cp_commit();
            cp_wait1();
        } else {
            cp_wait0();
        }
        __syncthreads();

        const __half* Kb = Ks + buf * KBUFH;
        float s[8][4];
#pragma unroll
        for (int n = 0; n < 8; ++n)
#pragma unroll
            for (int c = 0; c < 4; ++c) s[n][c] = 0.f;
#pragma unroll
        for (int ks = 0; ks < 4; ++ks) {
#pragma unroll
            for (int ng = 0; ng < 4; ++ng) {
                unsigned r0, r1, r2, r3;
                ldsm_x4h(r0, r1, r2, r3, &Kb[(brow_base + ng * 16) * ASTRH + ks * 16 + bko]);
                mma_f16(s[ng * 2][0], s[ng * 2][1], s[ng * 2][2], s[ng * 2][3],
                        qf[ks][0], qf[ks][1], qf[ks][2], qf[ks][3], r0, r1);
                mma_f16(s[ng * 2 + 1][0], s[ng * 2 + 1][1], s[ng * 2 + 1][2], s[ng * 2 + 1][3],
                        qf[ks][0], qf[ks][1], qf[ks][2], qf[ks][3], r2, r3);
            }
        }

#pragma unroll
        for (int n = 0; n < 8; ++n) {
#pragma unroll
            for (int c = 0; c < 4; ++c) {
                int key = key0 + n * 8 + pcol + (c & 1);
                int qg = t0 + prow0 + ((c >> 1) * 8);
                bool valid = (key >= 0) && (key < S_) && (key - qg <= W_) && (qg - key <= W_);
                if (!valid) s[n][c] = -1e38f;
            }
        }

        float mx0 = -1e30f, mx1 = -1e30f;
#pragma unroll
        for (int n = 0; n < 8; ++n) {
            mx0 = fmaxf(mx0, fmaxf(s[n][0], s[n][1]));
            mx1 = fmaxf(mx1, fmaxf(s[n][2], s[n][3]));
        }
        mx0 = fmaxf(mx0, __shfl_xor_sync(0xffffffffu, mx0, 1));
        mx0 = fmaxf(mx0, __shfl_xor_sync(0xffffffffu, mx0, 2));
        mx1 = fmaxf(mx1, __shfl_xor_sync(0xffffffffu, mx1, 1));
        mx1 = fmaxf(mx1, __shfl_xor_sync(0xffffffffu, mx1, 2));

        float mn0 = fmaxf(m0, mx0), mn1 = fmaxf(m1, mx1);
        float corr0 = exp2f(m0 - mn0), corr1 = exp2f(m1 - mn1);
        m0 = mn0; m1 = mn1;
        l0 *= corr0; l1 *= corr1;
#pragma unroll
        for (int n = 0; n < 8; ++n) {
            o[n][0] *= corr0; o[n][1] *= corr0;
            o[n][2] *= corr1; o[n][3] *= corr1;
        }

        unsigned pf[4][4];
#pragma unroll
        for (int j = 0; j < 4; ++j) {
            float p00 = exp2f(s[2 * j][0] - mn0);
            float p01 = exp2f(s[2 * j][1] - mn0);
            float p02 = exp2f(s[2 * j][2] - mn1);
            float p03 = exp2f(s[2 * j][3] - mn1);
            float p10 = exp2f(s[2 * j + 1][0] - mn0);
            float p11 = exp2f(s[2 * j + 1][1] - mn0);
            float p12 = exp2f(s[2 * j + 1][2] - mn1);
            float p13 = exp2f(s[2 * j + 1][3] - mn1);
            l0 += p00 + p01 + p10 + p11;
            l1 += p02 + p03 + p12 + p13;
            __half2 hh;
            hh = __floats2half2_rn(p00, p01); pf[j][0] = *reinterpret_cast<unsigned*>(&hh);
            hh = __floats2half2_rn(p02, p03); pf[j][1] = *reinterpret_cast<unsigned*>(&hh);
            hh = __floats2half2_rn(p10, p11); pf[j][2] = *reinterpret_cast<unsigned*>(&hh);
            hh = __floats2half2_rn(p12, p13); pf[j][3] = *reinterpret_cast<unsigned*>(&hh);
        }

        const __half* Vb = Vs + buf * KBUFH;
#pragma unroll
        for (int ks = 0; ks < 4; ++ks) {
#pragma unroll
            for (int ng = 0; ng < 4; ++ng) {
                unsigned r0, r1, r2, r3;
                ldsm_x4h_t(r0, r1, r2, r3,
                           &Vb[(ks * 16 + v_row) * ASTRH + ng * 16 + v_coff]);
                mma_f16(o[ng * 2][0], o[ng * 2][1], o[ng * 2][2], o[ng * 2][3],
                        pf[ks][0], pf[ks][1], pf[ks][2], pf[ks][3], r0, r1);
                mma_f16(o[ng * 2 + 1][0], o[ng * 2 + 1][1], o[ng * 2 + 1][2], o[ng * 2 + 1][3],
                        pf[ks][0], pf[ks][1], pf[ks][2], pf[ks][3], r2, r3);
            }
        }
        __syncthreads();
    }

    l0 += __shfl_xor_sync(0xffffffffu, l0, 1);
    l0 += __shfl_xor_sync(0xffffffffu, l0, 2);
    l1 += __shfl_xor_sync(0xffffffffu, l1, 1);
    l1 += __shfl_xor_sync(0xffffffffu, l1, 2);
    float inv0 = 1.f / l0, inv1 = 1.f / l1;

    __half* ob0 = out + ((size_t)(t0 + prow0) * B_ + b) * D_ + h * 64 + pcol;
    __half* ob1 = out + ((size_t)(t0 + prow0 + 8) * B_ + b) * D_ + h * 64 + pcol;
#pragma unroll
    for (int n = 0; n < 8; ++n) {
        *reinterpret_cast<__half2*>(ob0 + n * 8) = __floats2half2_rn(o[n][0] * inv0, o[n][1] * inv0);
        *reinterpret_cast<__half2*>(ob1 + n * 8) = __floats2half2_rn(o[n][2] * inv1, o[n][3] * inv1);
    }
}

// ---------------------------------------------------------------------------
// Warp-per-row fused residual-add(y fp16) + LayerNorm.
// ---------------------------------------------------------------------------
__global__ void __launch_bounds__(256) add_ln_h_kernel(
    const float* __restrict__ x, const __half* __restrict__ y,
    const float* __restrict__ g, const float* __restrict__ beta,
    float* __restrict__ out, __half* __restrict__ out16)
{
    const int row = blockIdx.x * 8 + (threadIdx.x >> 5);
    const int lane = threadIdx.x & 31;
    const size_t base = (size_t)row * D_;

    float v[4][4];
#pragma unroll
    for (int j = 0; j < 4; ++j) {
        int col = j * 128 + lane * 4;
        float4 xv = *reinterpret_cast<const float4*>(x + base + col);
        __half2 y0 = *reinterpret_cast<const __half2*>(y + base + col);
        __half2 y1 = *reinterpret_cast<const __half2*>(y + base + col + 2);
        float2 f0 = __half22float2(y0);
        float2 f1 = __half22float2(y1);
        v[j][0] = xv.x + f0.x;
        v[j][1] = xv.y + f0.y;
        v[j][2] = xv.z + f1.x;
        v[j][3] = xv.w + f1.y;
    }

    float s = 0.f, sq = 0.f;
#pragma unroll
    for (int j = 0; j < 4; ++j)
#pragma unroll
        for (int q = 0; q < 4; ++q) {
            s += v[j][q];
            sq += v[j][q] * v[j][q];
        }
#pragma unroll
    for (int o = 16; o > 0; o >>= 1) {
        s  += __shfl_xor_sync(0xffffffffu, s, o);
        sq += __shfl_xor_sync(0xffffffffu, sq, o);
    }
    float mean = s * (1.f / D_);
    float rstd = rsqrtf(sq * (1.f / D_) - mean * mean + EPS_);

#pragma unroll
    for (int j = 0; j < 4; ++j) {
        int col = j * 128 + lane * 4;
        float4 gv = *reinterpret_cast<const float4*>(g + col);
        float4 bv = *reinterpret_cast<const float4*>(beta + col);
        float r0 = (v[j][0] - mean) * rstd * gv.x + bv.x;
        float r1 = (v[j][1] - mean) * rstd * gv.y + bv.y;
        float r2 = (v[j][2] - mean) * rstd * gv.z + bv.z;
        float r3 = (v[j][3] - mean) * rstd * gv.w + bv.w;
        *reinterpret_cast<float4*>(out + base + col) = make_float4(r0, r1, r2, r3);
        if (out16) {
            *reinterpret_cast<__half2*>(out16 + base + col)     = __floats2half2_rn(r0, r1);
            *reinterpret_cast<__half2*>(out16 + base + col + 2) = __floats2half2_rn(r2, r3);
        }
    }
}

// ---------------------------------------------------------------------------
// Launch
// ---------------------------------------------------------------------------
extern "C" void kernel_launch(void* const* d_in, const int* in_sizes, int n_in,
                              void* d_out, int out_size)
{
    (void)in_sizes; (void)n_in; (void)out_size;
    const float* tgt        = (const float*)d_in[0];
    const float* memory     = (const float*)d_in[1];
    const float* in_proj_w  = (const float*)d_in[2];
    const float* in_proj_b  = (const float*)d_in[3];
    const float* out_proj_w = (const float*)d_in[4];
    const float* out_proj_b = (const float*)d_in[5];
    const float* sw_q_w = (const float*)d_in[6];
    const float* sw_q_b = (const float*)d_in[7];
    const float* sw_k_w = (const float*)d_in[8];
    const float* sw_k_b = (const float*)d_in[9];
    const float* sw_v_w = (const float*)d_in[10];
    const float* sw_v_b = (const float*)d_in[11];
    const float* sw_o_w = (const float*)d_in[12];
    const float* sw_o_b = (const float*)d_in[13];
    const float* lin1_w = (const float*)d_in[14];
    const float* lin1_b = (const float*)d_in[15];
    const float* lin2_w = (const float*)d_in[16];
    const float* lin2_b = (const float*)d_in[17];
    const float* n1_g = (const float*)d_in[18];
    const float* n1_b = (const float*)d_in[19];
    const float* n2_g = (const float*)d_in[20];
    const float* n2_b = (const float*)d_in[21];
    const float* n3_g = (const float*)d_in[22];
    const float* n3_b = (const float*)d_in[23];
    float* out = (float*)d_out;

    float* s = nullptr;
    cudaGetSymbolAddress((void**)&s, g_scratch);
    float* x1   = s + FOFF_X1;
    float* x2   = s + FOFF_X2;
    float* bcat = s + FOFF_BCAT;
    __half* hb = (__half*)(s + HALF_BASE_F);
    __half* qkv16    = hb + HOFF_QKV;
    __half* attn16   = hb + HOFF_ATTN;
    __half* swq16    = hb + HOFF_SWQ;
    __half* swkv16   = hb + HOFF_SWKV;
    __half* swattn16 = hb + HOFF_SWATTN;
    __half* hbuf16   = hb + HOFF_HBUF;
    __half* tgt16    = hb + HOFF_TGT;
    __half* mem16    = hb + HOFF_MEM;
    __half* x1h      = hb + HOFF_X1H;
    __half* x2h      = hb + HOFF_X2H;
    __half* w_in     = hb + HOFF_WIN;
    __half* w_out    = hb + HOFF_WOUT;
    __half* w_swq    = hb + HOFF_WSWQ;
    __half* w_swkv   = hb + HOFF_WSWKV;
    __half* w_swo    = hb + HOFF_WSWO;
    __half* w_lin1   = hb + HOFF_WLIN1;
    __half* w_lin2   = hb + HOFF_WLIN2;
    __half* proj16   = hb + HOFF_PROJ16;
    __half* ff16     = hb + HOFF_FF16;

    cudaFuncSetAttribute(self_attn_f16_kernel,
                         cudaFuncAttributeMaxDynamicSharedMemorySize, ATTN_SMEM);
    cudaFuncSetAttribute(sw_attn_f16_kernel,
                         cudaFuncAttributeMaxDynamicSharedMemorySize, SWA_SMEM);
    cudaFuncSetAttribute(gemm_f16_kernel,
                         cudaFuncAttributeMaxDynamicSharedMemorySize, G128_SMEM);
    cudaFuncSetAttribute(gemm_f16_dual_kernel,
                         cudaFuncAttributeMaxDynamicSharedMemorySize, G128_SMEM);
    cudaFuncSetAttribute(gemm_f16_n64_kernel,
                         cudaFuncAttributeMaxDynamicSharedMemorySize, G64_SMEM);

    // one fused convert (incl. KV weight concat + bias concat)
    f2h_multi_kernel<<<8192, 256>>>(tgt, tgt16, memory, mem16,
                                    in_proj_w, w_in, out_proj_w, w_out,
                                    sw_q_w, w_swq, sw_o_w, w_swo,
                                    lin1_w, w_lin1, lin2_w, w_lin2,
                                    sw_k_w, w_swkv, sw_v_w, w_swkv + 262144,
                                    sw_k_b, sw_v_b, bcat);

    // combined QKV (N=1536, 12 blocks) + fused KV (N=1024, 8 blocks)
    gemm_f16_dual_kernel<<<dim3(20, 32), 256, G128_SMEM>>>(
        tgt16, w_in, in_proj_b, qkv16, 3 * D_,
        mem16, w_swkv, bcat, swkv16, 1024,
        D_, 12);
    // self attention
    self_attn_f16_kernel<<<dim3(8, 32), 256, ATTN_SMEM>>>(qkv16, attn16);
    // out projection -> fp16
    gemm_f16_n64_kernel<<<dim3(8, 32), 256, G64_SMEM>>>(attn16, w_out, out_proj_b, proj16,
                                                        NROWS, D_, D_, 0, 1);
    // add + LN1 (warp-per-row)
    add_ln_h_kernel<<<NROWS / 8, 256>>>(tgt, proj16, n1_g, n1_b, x1, x1h);
    // sw q projection
    gemm_f16_n64_kernel<<<dim3(8, 32), 256, G64_SMEM>>>(x1h, w_swq, sw_q_b, swq16,
                                                        NROWS, D_, D_, 0, 1);
    // banded attention
    sw_attn_f16_kernel<<<dim3(8, 32), 256, SWA_SMEM>>>(swq16, swkv16, swattn16);
    // sw out projection -> fp16
    gemm_f16_n64_kernel<<<dim3(8, 32), 256, G64_SMEM>>>(swattn16, w_swo, sw_o_b, proj16,
                                                        NROWS, D_, D_, 0, 1);
    // add + LN2
    add_ln_h_kernel<<<NROWS / 8, 256>>>(x1, proj16, n2_g, n2_b, x2, x2h);
    // FFN up + ReLU
    gemm_f16_kernel<<<dim3(16, 32), 256, G128_SMEM>>>(x2h, w_lin1, lin1_b, hbuf16,
                                                      NROWS, DFF_, D_, 1, 1);
    // FFN down -> fp16
    gemm_f16_n64_kernel<<<dim3(8, 32), 256, G64_SMEM>>>(hbuf16, w_lin2, lin2_b, ff16,
                                                        NROWS, D_, DFF_, 0, 1);
    // add + LN3 -> output (fp32 only)
    add_ln_h_kernel<<<NROWS / 8, 256>>>(x2, ff16, n3_g, n3_b, out, nullptr);
}

// round 17
// speedup vs baseline: 1.0665x; 1.0187x over previous
#include <cuda_runtime.h>
#include <cuda_fp16.h>
#include <stdint.h>
#include <math.h>

#define T_ 1024
#define S_ 1024
#define B_ 4
#define D_ 512
#define H_ 8
#define HD_ 64
#define DFF_ 2048
#define W_ 16
#define NROWS (T_ * B_)
#define SCALE_ 0.125f
#define LOG2E_ 1.4426950408889634f
#define EPS_ 1e-5f

// fp32 region (float offsets)
#define FOFF_X1     0
#define FOFF_X2     2097152
#define FOFF_BCAT   4194304
#define HALF_BASE_F 5000000

// half region (half offsets)
#define HOFF_QKV    0
#define HOFF_ATTN   6291456
#define HOFF_SWQ    8388608
#define HOFF_SWKV   10485760
#define HOFF_SWATTN 14680064
#define HOFF_HBUF   16777216
#define HOFF_TGT    25165824
#define HOFF_MEM    27262976
#define HOFF_X1H    29360128
#define HOFF_X2H    31457280
#define HOFF_WIN    33554432
#define HOFF_WOUT   34340864
#define HOFF_WSWQ   34603008
#define HOFF_WSWKV  34865152
#define HOFF_WSWO   35389440
#define HOFF_WLIN1  35651584
#define HOFF_WLIN2  36700160
#define HOFF_PROJ16 37748736
#define HOFF_FF16   39845888

#define SCRATCH_FLOATS 33554432
__device__ float g_scratch[SCRATCH_FLOATS];

// ---------------------------------------------------------------------------
// PTX helpers
// ---------------------------------------------------------------------------
__device__ __forceinline__ void cp_async16(void* smem_ptr, const void* gmem_ptr) {
    unsigned saddr = (unsigned)__cvta_generic_to_shared(smem_ptr);
    asm volatile("cp.async.cg.shared.global [%0], [%1], 16;\n"
                 :: "r"(saddr), "l"(gmem_ptr));
}
__device__ __forceinline__ void cp_commit() {
    asm volatile("cp.async.commit_group;\n");
}
__device__ __forceinline__ void cp_wait0() {
    asm volatile("cp.async.wait_group 0;\n");
}
__device__ __forceinline__ void cp_wait1() {
    asm volatile("cp.async.wait_group 1;\n");
}
__device__ __forceinline__ void ldsm_x4h(unsigned& r0, unsigned& r1, unsigned& r2, unsigned& r3,
                                         const __half* p) {
    unsigned saddr = (unsigned)__cvta_generic_to_shared((void*)p);
    asm volatile("ldmatrix.sync.aligned.m8n8.x4.shared.b16 {%0,%1,%2,%3}, [%4];\n"
                 : "=r"(r0), "=r"(r1), "=r"(r2), "=r"(r3) : "r"(saddr));
}
__device__ __forceinline__ void ldsm_x4h_t(unsigned& r0, unsigned& r1, unsigned& r2, unsigned& r3,
                                           const __half* p) {
    unsigned saddr = (unsigned)__cvta_generic_to_shared((void*)p);
    asm volatile("ldmatrix.sync.aligned.m8n8.x4.trans.shared.b16 {%0,%1,%2,%3}, [%4];\n"
                 : "=r"(r0), "=r"(r1), "=r"(r2), "=r"(r3) : "r"(saddr));
}
__device__ __forceinline__ void mma_f16(float& c0, float& c1, float& c2, float& c3,
                                        unsigned a0, unsigned a1, unsigned a2, unsigned a3,
                                        unsigned b0, unsigned b1) {
    asm volatile("mma.sync.aligned.m16n8k16.row.col.f32.f16.f16.f32 "
                 "{%0,%1,%2,%3}, {%4,%5,%6,%7}, {%8,%9}, {%0,%1,%2,%3};\n"
                 : "+f"(c0), "+f"(c1), "+f"(c2), "+f"(c3)
                 : "r"(a0), "r"(a1), "r"(a2), "r"(a3), "r"(b0), "r"(b1));
}

// ---------------------------------------------------------------------------
// fp32->fp16 fused convert: 10 segments incl. KV weight concat + bias copy.
// ---------------------------------------------------------------------------
__global__ void __launch_bounds__(256) f2h_multi_kernel(
    const float* __restrict__ s0, __half* __restrict__ d0,
    const float* __restrict__ s1, __half* __restrict__ d1,
    const float* __restrict__ s2, __half* __restrict__ d2,
    const float* __restrict__ s3, __half* __restrict__ d3,
    const float* __restrict__ s4, __half* __restrict__ d4,
    const float* __restrict__ s5, __half* __restrict__ d5,
    const float* __restrict__ s6, __half* __restrict__ d6,
    const float* __restrict__ s7, __half* __restrict__ d7,
    const float* __restrict__ s8, __half* __restrict__ d8,
    const float* __restrict__ s9, __half* __restrict__ d9,
    const float* __restrict__ kb, const float* __restrict__ vb,
    float* __restrict__ bcat)
{
    if (blockIdx.x == 0) {
        int t = threadIdx.x;
        bcat[t] = kb[t];          bcat[512 + t] = vb[t];
        bcat[256 + t] = kb[256 + t]; bcat[768 + t] = vb[256 + t];
    }
    int idx = (blockIdx.x * 256 + threadIdx.x) * 4;
    const float* src; __half* dst; int off;
    if      (idx < 2097152) { src = s0; dst = d0; off = idx; }
    else if (idx < 4194304) { src = s1; dst = d1; off = idx - 2097152; }
    else if (idx < 4980736) { src = s2; dst = d2; off = idx - 4194304; }
    else if (idx < 5242880) { src = s3; dst = d3; off = idx - 4980736; }
    else if (idx < 5505024) { src = s4; dst = d4; off = idx - 5242880; }
    else if (idx < 5767168) { src = s5; dst = d5; off = idx - 5505024; }
    else if (idx < 6815744) { src = s6; dst = d6; off = idx - 5767168; }
    else if (idx < 7864320) { src = s7; dst = d7; off = idx - 6815744; }
    else if (idx < 8126464) { src = s8; dst = d8; off = idx - 7864320; }
    else                    { src = s9; dst = d9; off = idx - 8126464; }
    float4 v = *reinterpret_cast<const float4*>(src + off);
    *reinterpret_cast<__half2*>(dst + off)     = __floats2half2_rn(v.x, v.y);
    *reinterpret_cast<__half2*>(dst + off + 2) = __floats2half2_rn(v.z, v.w);
}

// ---------------------------------------------------------------------------
// FP16 GEMM 128x128 core, BK=64, 3-stage pipeline.
// ---------------------------------------------------------------------------
#define STR64 72
#define ASTG (128 * STR64)
#define G128_SMEM (6 * ASTG * 2)

__device__ __forceinline__ void gemm128_body(
    const __half* __restrict__ A, const __half* __restrict__ Wt,
    const float* __restrict__ bias, void* __restrict__ Cout,
    int N, int K, int relu, int out16, int m0, int n0, __half* sg)
{
    __half* As = sg;
    __half* Bs = sg + 3 * ASTG;

    const int tid  = threadIdx.x;
    const int wid  = tid >> 5;
    const int lane = tid & 31;
    const int wm   = (wid & 3) * 32;
    const int wn   = (wid >> 2) * 64;

    float acc[2][8][4];
#pragma unroll
    for (int i = 0; i < 2; ++i)
#pragma unroll
        for (int j = 0; j < 8; ++j)
#pragma unroll
            for (int q = 0; q < 4; ++q) acc[i][j][q] = 0.f;

    const int ntiles = K / 64;
    const __half* Abase = A + (size_t)m0 * K;
    const __half* Bbase = Wt + (size_t)n0 * K;

    auto load_stage = [&](int t, int st) {
        int k0 = t * 64;
        __half* Ad = As + st * ASTG;
        __half* Bd = Bs + st * ASTG;
#pragma unroll
        for (int it = 0; it < 4; ++it) {
            int idx = it * 256 + tid;
            int row = idx >> 3, col = (idx & 7) * 8;
            cp_async16(&Ad[row * STR64 + col], Abase + (size_t)row * K + k0 + col);
            cp_async16(&Bd[row * STR64 + col], Bbase + (size_t)row * K + k0 + col);
        }
    };

    load_stage(0, 0); cp_commit();
    load_stage(1, 1); cp_commit();

    const int a_row = wm + (lane & 15);
    const int a_koff = (lane >> 4) * 8;
    const int b_row_base = wn + (lane & 7) + ((lane >> 4) * 8);
    const int b_koff = ((lane >> 3) & 1) * 8;

    for (int t = 0; t < ntiles; ++t) {
        cp_wait1();
        __syncthreads();

        int ps = t + 2;
        if (ps < ntiles) load_stage(ps, ps % 3);
        cp_commit();

        const int buf = t % 3;
        const __half* Ab = As + buf * ASTG;
        const __half* Bb = Bs + buf * ASTG;
#pragma unroll
        for (int ks = 0; ks < 4; ++ks) {
            unsigned a[2][4];
            unsigned b[8][2];
#pragma unroll
            for (int im = 0; im < 2; ++im)
                ldsm_x4h(a[im][0], a[im][1], a[im][2], a[im][3],
                         &Ab[(a_row + im * 16) * STR64 + ks * 16 + a_koff]);
#pragma unroll
            for (int ng = 0; ng < 4; ++ng) {
                unsigned r0, r1, r2, r3;
                ldsm_x4h(r0, r1, r2, r3,
                         &Bb[(b_row_base + ng * 16) * STR64 + ks * 16 + b_koff]);
                b[ng * 2][0] = r0; b[ng * 2][1] = r1;
                b[ng * 2 + 1][0] = r2; b[ng * 2 + 1][1] = r3;
            }
#pragma unroll
            for (int im = 0; im < 2; ++im)
#pragma unroll
                for (int in = 0; in < 8; ++in)
                    mma_f16(acc[im][in][0], acc[im][in][1], acc[im][in][2], acc[im][in][3],
                            a[im][0], a[im][1], a[im][2], a[im][3],
                            b[in][0], b[in][1]);
        }
    }

    const int row_base = m0 + wm + (lane >> 2);
    const int col_base = n0 + wn + (lane & 3) * 2;
#pragma unroll
    for (int im = 0; im < 2; ++im) {
#pragma unroll
        for (int in = 0; in < 8; ++in) {
            int col = col_base + in * 8;
            float b0 = bias[col], b1 = bias[col + 1];
            int r0 = row_base + im * 16;
            float v0 = acc[im][in][0] + b0;
            float v1 = acc[im][in][1] + b1;
            float v2 = acc[im][in][2] + b0;
            float v3 = acc[im][in][3] + b1;
            if (relu) {
                v0 = fmaxf(v0, 0.f); v1 = fmaxf(v1, 0.f);
                v2 = fmaxf(v2, 0.f); v3 = fmaxf(v3, 0.f);
            }
            if (out16) {
                __half* C = (__half*)Cout;
                *reinterpret_cast<__half2*>(&C[(size_t)r0 * N + col]) = __floats2half2_rn(v0, v1);
                *reinterpret_cast<__half2*>(&C[(size_t)(r0 + 8) * N + col]) = __floats2half2_rn(v2, v3);
            } else {
                float* C = (float*)Cout;
                C[(size_t)r0 * N + col] = v0;
                C[(size_t)r0 * N + col + 1] = v1;
                C[(size_t)(r0 + 8) * N + col] = v2;
                C[(size_t)(r0 + 8) * N + col + 1] = v3;
            }
        }
    }
}

__global__ void __launch_bounds__(256, 2) gemm_f16_kernel(
    const __half* __restrict__ A, const __half* __restrict__ Wt,
    const float* __restrict__ bias, void* __restrict__ Cout,
    int M, int N, int K, int relu, int out16)
{
    extern __shared__ __half sg[];
    gemm128_body(A, Wt, bias, Cout, N, K, relu, out16,
                 blockIdx.y * 128, blockIdx.x * 128, sg);
}

__global__ void __launch_bounds__(256, 2) gemm_f16_dual_kernel(
    const __half* __restrict__ A1, const __half* __restrict__ W1,
    const float* __restrict__ b1, void* __restrict__ C1, int N1,
    const __half* __restrict__ A2, const __half* __restrict__ W2,
    const float* __restrict__ b2, void* __restrict__ C2, int N2,
    int K, int split)
{
    extern __shared__ __half sg[];
    if ((int)blockIdx.x < split)
        gemm128_body(A1, W1, b1, C1, N1, K, 0, 1,
                     blockIdx.y * 128, blockIdx.x * 128, sg);
    else
        gemm128_body(A2, W2, b2, C2, N2, K, 0, 1,
                     blockIdx.y * 128, (blockIdx.x - split) * 128, sg);
}

// ---------------------------------------------------------------------------
// FP16 GEMM 128x64, 128 threads (4 warps), warp tile 64x32, BK=64, 2-stage.
// smem: 2 x (128+64)x72 halfs = 55296 B -> up to 4 CTAs/SM.
// Inner loop per k16: 6 ldsm vs 16 mma (tensor-dominant).
// ---------------------------------------------------------------------------
#define BSTG64 (64 * STR64)
#define G64_SMEM (2 * (ASTG + BSTG64) * 2)

__global__ void __launch_bounds__(128, 4) gemm_f16_n64_kernel(
    const __half* __restrict__ A, const __half* __restrict__ Wt,
    const float* __restrict__ bias, void* __restrict__ Cout,
    int M, int N, int K, int relu, int out16)
{
    extern __shared__ __half sg[];
    __half* As = sg;
    __half* Bs = sg + 2 * ASTG;

    const int tid  = threadIdx.x;
    const int wid  = tid >> 5;
    const int lane = tid & 31;
    const int wm   = (wid & 1) * 64;
    const int wn   = (wid >> 1) * 32;
    const int m0   = blockIdx.y * 128;
    const int n0   = blockIdx.x * 64;

    float acc[4][4][4];
#pragma unroll
    for (int i = 0; i < 4; ++i)
#pragma unroll
        for (int j = 0; j < 4; ++j)
#pragma unroll
            for (int q = 0; q < 4; ++q) acc[i][j][q] = 0.f;

    const int ntiles = K / 64;
    const __half* Abase = A + (size_t)m0 * K;
    const __half* Bbase = Wt + (size_t)n0 * K;

    // loaders: A 128x64 halfs (8 it of 128 thr), B 64x64 (4 it)
    auto load_stage = [&](int t, int st) {
        int k0 = t * 64;
        __half* Ad = As + st * ASTG;
        __half* Bd = Bs + st * BSTG64;
#pragma unroll
        for (int it = 0; it < 8; ++it) {
            int idx = it * 128 + tid;
            int row = idx >> 3, col = (idx & 7) * 8;
            cp_async16(&Ad[row * STR64 + col], Abase + (size_t)row * K + k0 + col);
        }
#pragma unroll
        for (int it = 0; it < 4; ++it) {
            int idx = it * 128 + tid;
            int row = idx >> 3, col = (idx & 7) * 8;
            cp_async16(&Bd[row * STR64 + col], Bbase + (size_t)row * K + k0 + col);
        }
    };

    load_stage(0, 0); cp_commit();

    const int a_row = wm + (lane & 15);
    const int a_koff = (lane >> 4) * 8;
    const int b_row_base = wn + (lane & 7) + ((lane >> 4) * 8);
    const int b_koff = ((lane >> 3) & 1) * 8;

    for (int t = 0; t < ntiles; ++t) {
        cp_wait0();
        __syncthreads();

        if (t + 1 < ntiles) {
            load_stage(t + 1, (t + 1) & 1);
            cp_commit();
        }

        const int buf = t & 1;
        const __half* Ab = As + buf * ASTG;
        const __half* Bb = Bs + buf * BSTG64;
#pragma unroll
        for (int ks = 0; ks < 4; ++ks) {
            unsigned a[4][4];
            unsigned b[4][2];
#pragma unroll
            for (int im = 0; im < 4; ++im)
                ldsm_x4h(a[im][0], a[im][1], a[im][2], a[im][3],
                         &Ab[(a_row + im * 16) * STR64 + ks * 16 + a_koff]);
#pragma unroll
            for (int ng = 0; ng < 2; ++ng) {
                unsigned r0, r1, r2, r3;
                ldsm_x4h(r0, r1, r2, r3,
                         &Bb[(b_row_base + ng * 16) * STR64 + ks * 16 + b_koff]);
                b[ng * 2][0] = r0; b[ng * 2][1] = r1;
                b[ng * 2 + 1][0] = r2; b[ng * 2 + 1][1] = r3;
            }
#pragma unroll
            for (int im = 0; im < 4; ++im)
#pragma unroll
                for (int in = 0; in < 4; ++in)
                    mma_f16(acc[im][in][0], acc[im][in][1], acc[im][in][2], acc[im][in][3],
                            a[im][0], a[im][1], a[im][2], a[im][3],
                            b[in][0], b[in][1]);
        }
    }

    const int row_base = m0 + wm + (lane >> 2);
    const int col_base = n0 + wn + (lane & 3) * 2;
#pragma unroll
    for (int im = 0; im < 4; ++im) {
#pragma unroll
        for (int in = 0; in < 4; ++in) {
            int col = col_base + in * 8;
            float b0 = bias[col], b1 = bias[col + 1];
            int r0 = row_base + im * 16;
            float v0 = acc[im][in][0] + b0;
            float v1 = acc[im][in][1] + b1;
            float v2 = acc[im][in][2] + b0;
            float v3 = acc[im][in][3] + b1;
            if (relu) {
                v0 = fmaxf(v0, 0.f); v1 = fmaxf(v1, 0.f);
                v2 = fmaxf(v2, 0.f); v3 = fmaxf(v3, 0.f);
            }
            if (out16) {
                __half* C = (__half*)Cout;
                *reinterpret_cast<__half2*>(&C[(size_t)r0 * N + col]) = __floats2half2_rn(v0, v1);
                *reinterpret_cast<__half2*>(&C[(size_t)(r0 + 8) * N + col]) = __floats2half2_rn(v2, v3);
            } else {
                float* C = (float*)Cout;
                C[(size_t)r0 * N + col] = v0;
                C[(size_t)r0 * N + col + 1] = v1;
                C[(size_t)(r0 + 8) * N + col] = v2;
                C[(size_t)(r0 + 8) * N + col + 1] = v3;
            }
        }
    }
}

// ---------------------------------------------------------------------------
// FP16 flash self-attention: 128-key tiles, register P, exp2 softmax.
// ---------------------------------------------------------------------------
#define ASTRH 72
#define KB128 (128 * ASTRH)
#define ROWH 6144
#define ATTN_SMEM ((128 + 4 * 128) * ASTRH * 2)

__global__ void __launch_bounds__(256, 2) self_attn_f16_kernel(
    const __half* __restrict__ qkv, __half* __restrict__ out)
{
    extern __shared__ __half smh[];
    __half* Ps = smh;
    __half* Ks = smh + 128 * ASTRH;
    __half* Vs = Ks + 2 * KB128;

    const int tid = threadIdx.x;
    const int wid = tid >> 5;
    const int lane = tid & 31;
    const int b = blockIdx.y >> 3;
    const int h = blockIdx.y & 7;
    const int t0 = blockIdx.x * 128;
    const int wm = wid * 16;

    const __half* qbase = qkv + ((size_t)t0 * B_ + b) * 1536 + h * 64;
    const __half* kroot = qkv + (size_t)b * 1536 + 512 + h * 64;
    const __half* vroot = qkv + (size_t)b * 1536 + 1024 + h * 64;

#pragma unroll
    for (int i = 0; i < 4; ++i) {
        int idx = i * 256 + tid;
        int r = idx >> 3, c = (idx & 7) * 8;
        cp_async16(&Ps[r * ASTRH + c], qbase + (size_t)r * ROWH + c);
    }
#pragma unroll
    for (int i = 0; i < 4; ++i) {
        int idx = i * 256 + tid;
        int r = idx >> 3, c = (idx & 7) * 8;
        cp_async16(&Ks[r * ASTRH + c], kroot + (size_t)r * ROWH + c);
        cp_async16(&Vs[r * ASTRH + c], vroot + (size_t)r * ROWH + c);
    }
    cp_commit();
    cp_wait0();
    __syncthreads();

    unsigned qf[4][4];
    {
        const __half2 sc2 = __float2half2_rn(SCALE_ * LOG2E_);
        const int qrow = wm + (lane & 15);
        const int qko = (lane >> 4) * 8;
#pragma unroll
        for (int ks = 0; ks < 4; ++ks) {
            unsigned r0, r1, r2, r3;
            ldsm_x4h(r0, r1, r2, r3, &Ps[qrow * ASTRH + ks * 16 + qko]);
            unsigned rr[4] = {r0, r1, r2, r3};
#pragma unroll
            for (int j = 0; j < 4; ++j) {
                __half2 v = *reinterpret_cast<__half2*>(&rr[j]);
                v = __hmul2(v, sc2);
                qf[ks][j] = *reinterpret_cast<unsigned*>(&v);
            }
        }
    }

    float o[8][4];
#pragma unroll
    for (int n = 0; n < 8; ++n)
#pragma unroll
        for (int c = 0; c < 4; ++c) o[n][c] = 0.f;
    float m0 = -1e30f, m1 = -1e30f, l0 = 0.f, l1 = 0.f;

    const int brow_base = (lane & 7) + ((lane >> 4) * 8);
    const int bko = ((lane >> 3) & 1) * 8;
    const int prow0 = wm + (lane >> 2);
    const int pcol = 2 * (lane & 3);
    const int v_row = lane & 15;
    const int v_coff = (lane >> 4) * 8;

    for (int kt = 0; kt < 8; ++kt) {
        const int buf = kt & 1;

        if (kt + 1 < 8) {
            const __half* kb = kroot + (size_t)(kt + 1) * 128 * ROWH;
            const __half* vb = vroot + (size_t)(kt + 1) * 128 * ROWH;
            __half* kd = Ks + (buf ^ 1) * KB128;
            __half* vd = Vs + (buf ^ 1) * KB128;
#pragma unroll
            for (int i = 0; i < 4; ++i) {
                int idx = i * 256 + tid;
                int r = idx >> 3, c = (idx & 7) * 8;
                cp_async16(&kd[r * ASTRH + c], kb + (size_t)r * ROWH + c);
                cp_async16(&vd[r * ASTRH + c], vb + (size_t)r * ROWH + c);
            }
            cp_commit();
            cp_wait1();
        } else {
            cp_wait0();
        }
        __syncthreads();

#pragma unroll
        for (int half = 0; half < 2; ++half) {
            const __half* Kb = Ks + buf * KB128 + half * 64 * ASTRH;
            const __half* Vb = Vs + buf * KB128 + half * 64 * ASTRH;

            float s[8][4];
#pragma unroll
            for (int n = 0; n < 8; ++n)
#pragma unroll
                for (int c = 0; c < 4; ++c) s[n][c] = 0.f;
#pragma unroll
            for (int ks = 0; ks < 4; ++ks) {
#pragma unroll
                for (int ng = 0; ng < 4; ++ng) {
                    unsigned r0, r1, r2, r3;
                    ldsm_x4h(r0, r1, r2, r3, &Kb[(brow_base + ng * 16) * ASTRH + ks * 16 + bko]);
                    mma_f16(s[ng * 2][0], s[ng * 2][1], s[ng * 2][2], s[ng * 2][3],
                            qf[ks][0], qf[ks][1], qf[ks][2], qf[ks][3], r0, r1);
                    mma_f16(s[ng * 2 + 1][0], s[ng * 2 + 1][1], s[ng * 2 + 1][2], s[ng * 2 + 1][3],
                            qf[ks][0], qf[ks][1], qf[ks][2], qf[ks][3], r2, r3);
                }
            }

            float mx0 = -1e30f, mx1 = -1e30f;
#pragma unroll
            for (int n = 0; n < 8; ++n) {
                mx0 = fmaxf(mx0, fmaxf(s[n][0], s[n][1]));
                mx1 = fmaxf(mx1, fmaxf(s[n][2], s[n][3]));
            }
            mx0 = fmaxf(mx0, __shfl_xor_sync(0xffffffffu, mx0, 1));
            mx0 = fmaxf(mx0, __shfl_xor_sync(0xffffffffu, mx0, 2));
            mx1 = fmaxf(mx1, __shfl_xor_sync(0xffffffffu, mx1, 1));
            mx1 = fmaxf(mx1, __shfl_xor_sync(0xffffffffu, mx1, 2));

            float mn0 = fmaxf(m0, mx0), mn1 = fmaxf(m1, mx1);
            float corr0 = exp2f(m0 - mn0), corr1 = exp2f(m1 - mn1);
            m0 = mn0; m1 = mn1;
            l0 *= corr0; l1 *= corr1;
#pragma unroll
            for (int n = 0; n < 8; ++n) {
                o[n][0] *= corr0; o[n][1] *= corr0;
                o[n][2] *= corr1; o[n][3] *= corr1;
            }

            unsigned pf[4][4];
#pragma unroll
            for (int j = 0; j < 4; ++j) {
                float p00 = exp2f(s[2 * j][0] - mn0);
                float p01 = exp2f(s[2 * j][1] - mn0);
                float p02 = exp2f(s[2 * j][2] - mn1);
                float p03 = exp2f(s[2 * j][3] - mn1);
                float p10 = exp2f(s[2 * j + 1][0] - mn0);
                float p11 = exp2f(s[2 * j + 1][1] - mn0);
                float p12 = exp2f(s[2 * j + 1][2] - mn1);
                float p13 = exp2f(s[2 * j + 1][3] - mn1);
                l0 += p00 + p01 + p10 + p11;
                l1 += p02 + p03 + p12 + p13;
                __half2 hh;
                hh = __floats2half2_rn(p00, p01); pf[j][0] = *reinterpret_cast<unsigned*>(&hh);
                hh = __floats2half2_rn(p02, p03); pf[j][1] = *reinterpret_cast<unsigned*>(&hh);
                hh = __floats2half2_rn(p10, p11); pf[j][2] = *reinterpret_cast<unsigned*>(&hh);
                hh = __floats2half2_rn(p12, p13); pf[j][3] = *reinterpret_cast<unsigned*>(&hh);
            }

#pragma unroll
            for (int ks = 0; ks < 4; ++ks) {
#pragma unroll
                for (int ng = 0; ng < 4; ++ng) {
                    unsigned r0, r1, r2, r3;
                    ldsm_x4h_t(r0, r1, r2, r3,
                               &Vb[(ks * 16 + v_row) * ASTRH + ng * 16 + v_coff]);
                    mma_f16(o[ng * 2][0], o[ng * 2][1], o[ng * 2][2], o[ng * 2][3],
                            pf[ks][0], pf[ks][1], pf[ks][2], pf[ks][3], r0, r1);
                    mma_f16(o[ng * 2 + 1][0], o[ng * 2 + 1][1], o[ng * 2 + 1][2], o[ng * 2 + 1][3],
                            pf[ks][0], pf[ks][1], pf[ks][2], pf[ks][3], r2, r3);
                }
            }
        }
        __syncthreads();
    }

    l0 += __shfl_xor_sync(0xffffffffu, l0, 1);
    l0 += __shfl_xor_sync(0xffffffffu, l0, 2);
    l1 += __shfl_xor_sync(0xffffffffu, l1, 1);
    l1 += __shfl_xor_sync(0xffffffffu, l1, 2);
    float inv0 = 1.f / l0, inv1 = 1.f / l1;

    __half* ob0 = out + ((size_t)(t0 + prow0) * B_ + b) * D_ + h * 64 + pcol;
    __half* ob1 = out + ((size_t)(t0 + prow0 + 8) * B_ + b) * D_ + h * 64 + pcol;
#pragma unroll
    for (int n = 0; n < 8; ++n) {
        *reinterpret_cast<__half2*>(ob0 + n * 8) = __floats2half2_rn(o[n][0] * inv0, o[n][1] * inv0);
        *reinterpret_cast<__half2*>(ob1 + n * 8) = __floats2half2_rn(o[n][2] * inv1, o[n][3] * inv1);
    }
}

// ---------------------------------------------------------------------------
// FP16 banded sliding-window attention (register P, exp2 softmax).
// ---------------------------------------------------------------------------
#define KBUFH (64 * ASTRH)
#define SWA_SMEM ((128 + 4 * 64) * ASTRH * 2)

__global__ void __launch_bounds__(256, 2) sw_attn_f16_kernel(
    const __half* __restrict__ q, const __half* __restrict__ kv,
    __half* __restrict__ out)
{
    extern __shared__ __half smh[];
    __half* Ps = smh;
    __half* Ks = smh + 128 * ASTRH;
    __half* Vs = Ks + 2 * KBUFH;

    const int tid = threadIdx.x;
    const int wid = tid >> 5;
    const int lane = tid & 31;
    const int b = blockIdx.y >> 3;
    const int h = blockIdx.y & 7;
    const int t0 = blockIdx.x * 128;
    const int wm = wid * 16;

#pragma unroll
    for (int i = 0; i < 4; ++i) {
        int idx = i * 256 + tid;
        int r = idx >> 3, c = (idx & 7) * 8;
        cp_async16(&Ps[r * ASTRH + c],
                   q + ((size_t)(t0 + r) * B_ + b) * D_ + h * 64 + c);
    }
    {
        int key0 = t0 - 16;
#pragma unroll
        for (int i = 0; i < 2; ++i) {
            int idx = i * 256 + tid;
            int r = idx >> 3, c = (idx & 7) * 8;
            int key = min(max(key0 + r, 0), S_ - 1);
            const __half* base = kv + ((size_t)key * B_ + b) * 1024 + h * 64;
            cp_async16(&Ks[r * ASTRH + c], base + c);
            cp_async16(&Vs[r * ASTRH + c], base + 512 + c);
        }
    }
    cp_commit();
    cp_wait0();
    __syncthreads();

    unsigned qf[4][4];
    {
        const __half2 sc2 = __float2half2_rn(SCALE_ * LOG2E_);
        const int qrow = wm + (lane & 15);
        const int qko = (lane >> 4) * 8;
#pragma unroll
        for (int ks = 0; ks < 4; ++ks) {
            unsigned r0, r1, r2, r3;
            ldsm_x4h(r0, r1, r2, r3, &Ps[qrow * ASTRH + ks * 16 + qko]);
            unsigned rr[4] = {r0, r1, r2, r3};
#pragma unroll
            for (int j = 0; j < 4; ++j) {
                __half2 v = *reinterpret_cast<__half2*>(&rr[j]);
                v = __hmul2(v, sc2);
                qf[ks][j] = *reinterpret_cast<unsigned*>(&v);
            }
        }
    }

    float o[8][4];
#pragma unroll
    for (int n = 0; n < 8; ++n)
#pragma unroll
        for (int c = 0; c < 4; ++c) o[n][c] = 0.f;
    float m0 = -1e30f, m1 = -1e30f, l0 = 0.f, l1 = 0.f;

    const int brow_base = (lane & 7) + ((lane >> 4) * 8);
    const int bko = ((lane >> 3) & 1) * 8;
    const int prow0 = wm + (lane >> 2);
    const int pcol = 2 * (lane & 3);
    const int v_row = lane & 15;
    const int v_coff = (lane >> 4) * 8;

    for (int kt = 0; kt < 3; ++kt) {
        const int buf = kt & 1;
        const int key0 = t0 - 16 + kt * 64;

        if (kt + 1 < 3) {
            int nk0 = t0 - 16 + (kt + 1) * 64;
            __half* kd = Ks + (buf ^ 1) * KBUFH;
            __half* vd = Vs + (buf ^ 1) * KBUFH;
#pragma unroll
            for (int i = 0; i < 2; ++i) {
                int idx = i * 256 + tid;
                int r = idx >> 3, c = (idx & 7) * 8;
                int key = min(max(nk0 + r, 0), S_ - 1);
                const __half* base = kv + ((size_t)key * B_ + b) * 1024 + h * 64;
                cp_async16(&kd[r * ASTRH + c], base + c);
                cp_async16(&vd[r * ASTRH + c], base + 512 + c);
            }
            cp_commit();
            cp_wait1();
        } else {
            cp_wait0();
        }
        __syncthreads();

        const __half* Kb = Ks + buf * KBUFH;
        float s[8][4];
#pragma unroll
        for (int n = 0; n < 8; ++n)
#pragma unroll
            for (int c = 0; c < 4; ++c) s[n][c] = 0.f;
#pragma unroll
        for (int ks = 0; ks < 4; ++ks) {
#pragma unroll
            for (int ng = 0; ng < 4; ++ng) {
                unsigned r0, r1, r2, r3;
                ldsm_x4h(r0, r1, r2, r3, &Kb[(brow_base + ng * 16) * ASTRH + ks * 16 + bko]);
                mma_f16(s[ng * 2][0], s[ng * 2][1], s[ng * 2][2], s[ng * 2][3],
                        qf[ks][0], qf[ks][1], qf[ks][2], qf[ks][3], r0, r1);
                mma_f16(s[ng * 2 + 1][0], s[ng * 2 + 1][1], s[ng * 2 + 1][2], s[ng * 2 + 1][3],
                        qf[ks][0], qf[ks][1], qf[ks][2], qf[ks][3], r2, r3);
            }
        }

#pragma unroll
        for (int n = 0; n < 8; ++n) {
#pragma unroll
            for (int c = 0; c < 4; ++c) {
                int key = key0 + n * 8 + pcol + (c & 1);
                int qg = t0 + prow0 + ((c >> 1) * 8);
                bool valid = (key >= 0) && (key < S_) && (key - qg <= W_) && (qg - key <= W_);
                if (!valid) s[n][c] = -1e38f;
            }
        }

        float mx0 = -1e30f, mx1 = -1e30f;
#pragma unroll
        for (int n = 0; n < 8; ++n) {
            mx0 = fmaxf(mx0, fmaxf(s[n][0], s[n][1]));
            mx1 = fmaxf(mx1, fmaxf(s[n][2], s[n][3]));
        }
        mx0 = fmaxf(mx0, __shfl_xor_sync(0xffffffffu, mx0, 1));
        mx0 = fmaxf(mx0, __shfl_xor_sync(0xffffffffu, mx0, 2));
        mx1 = fmaxf(mx1, __shfl_xor_sync(0xffffffffu, mx1, 1));
        mx1 = fmaxf(mx1, __shfl_xor_sync(0xffffffffu, mx1, 2));

        float mn0 = fmaxf(m0, mx0), mn1 = fmaxf(m1, mx1);
        float corr0 = exp2f(m0 - mn0), corr1 = exp2f(m1 - mn1);
        m0 = mn0; m1 = mn1;
        l0 *= corr0; l1 *= corr1;
#pragma unroll
        for (int n = 0; n < 8; ++n) {
            o[n][0] *= corr0; o[n][1] *= corr0;
            o[n][2] *= corr1; o[n][3] *= corr1;
        }

        unsigned pf[4][4];
#pragma unroll
        for (int j = 0; j < 4; ++j) {
            float p00 = exp2f(s[2 * j][0] - mn0);
            float p01 = exp2f(s[2 * j][1] - mn0);
            float p02 = exp2f(s[2 * j][2] - mn1);
            float p03 = exp2f(s[2 * j][3] - mn1);
            float p10 = exp2f(s[2 * j + 1][0] - mn0);
            float p11 = exp2f(s[2 * j + 1][1] - mn0);
            float p12 = exp2f(s[2 * j + 1][2] - mn1);
            float p13 = exp2f(s[2 * j + 1][3] - mn1);
            l0 += p00 + p01 + p10 + p11;
            l1 += p02 + p03 + p12 + p13;
            __half2 hh;
            hh = __floats2half2_rn(p00, p01); pf[j][0] = *reinterpret_cast<unsigned*>(&hh);
            hh = __floats2half2_rn(p02, p03); pf[j][1] = *reinterpret_cast<unsigned*>(&hh);
            hh = __floats2half2_rn(p10, p11); pf[j][2] = *reinterpret_cast<unsigned*>(&hh);
            hh = __floats2half2_rn(p12, p13); pf[j][3] = *reinterpret_cast<unsigned*>(&hh);
        }

        const __half* Vb = Vs + buf * KBUFH;
#pragma unroll
        for (int ks = 0; ks < 4; ++ks) {
#pragma unroll
            for (int ng = 0; ng < 4; ++ng) {
                unsigned r0, r1, r2, r3;
                ldsm_x4h_t(r0, r1, r2, r3,
                           &Vb[(ks * 16 + v_row) * ASTRH + ng * 16 + v_coff]);
                mma_f16(o[ng * 2][0], o[ng * 2][1], o[ng * 2][2], o[ng * 2][3],
                        pf[ks][0], pf[ks][1], pf[ks][2], pf[ks][3], r0, r1);
                mma_f16(o[ng * 2 + 1][0], o[ng * 2 + 1][1], o[ng * 2 + 1][2], o[ng * 2 + 1][3],
                        pf[ks][0], pf[ks][1], pf[ks][2], pf[ks][3], r2, r3);
            }
        }
        __syncthreads();
    }

    l0 += __shfl_xor_sync(0xffffffffu, l0, 1);
    l0 += __shfl_xor_sync(0xffffffffu, l0, 2);
    l1 += __shfl_xor_sync(0xffffffffu, l1, 1);
    l1 += __shfl_xor_sync(0xffffffffu, l1, 2);
    float inv0 = 1.f / l0, inv1 = 1.f / l1;

    __half* ob0 = out + ((size_t)(t0 + prow0) * B_ + b) * D_ + h * 64 + pcol;
    __half* ob1 = out + ((size_t)(t0 + prow0 + 8) * B_ + b) * D_ + h * 64 + pcol;
#pragma unroll
    for (int n = 0; n < 8; ++n) {
        *reinterpret_cast<__half2*>(ob0 + n * 8) = __floats2half2_rn(o[n][0] * inv0, o[n][1] * inv0);
        *reinterpret_cast<__half2*>(ob1 + n * 8) = __floats2half2_rn(o[n][2] * inv1, o[n][3] * inv1);
    }
}

// ---------------------------------------------------------------------------
// Warp-per-row fused residual-add(y fp16) + LayerNorm.
// ---------------------------------------------------------------------------
__global__ void __launch_bounds__(256) add_ln_h_kernel(
    const float* __restrict__ x, const __half* __restrict__ y,
    const float* __restrict__ g, const float* __restrict__ beta,
    float* __restrict__ out, __half* __restrict__ out16)
{
    const int row = blockIdx.x * 8 + (threadIdx.x >> 5);
    const int lane = threadIdx.x & 31;
    const size_t base = (size_t)row * D_;

    float v[4][4];
#pragma unroll
    for (int j = 0; j < 4; ++j) {
        int col = j * 128 + lane * 4;
        float4 xv = *reinterpret_cast<const float4*>(x + base + col);
        __half2 y0 = *reinterpret_cast<const __half2*>(y + base + col);
        __half2 y1 = *reinterpret_cast<const __half2*>(y + base + col + 2);
        float2 f0 = __half22float2(y0);
        float2 f1 = __half22float2(y1);
        v[j][0] = xv.x + f0.x;
        v[j][1] = xv.y + f0.y;
        v[j][2] = xv.z + f1.x;
        v[j][3] = xv.w + f1.y;
    }

    float s = 0.f, sq = 0.f;
#pragma unroll
    for (int j = 0; j < 4; ++j)
#pragma unroll
        for (int q = 0; q < 4; ++q) {
            s += v[j][q];
            sq += v[j][q] * v[j][q];
        }
#pragma unroll
    for (int o = 16; o > 0; o >>= 1) {
        s  += __shfl_xor_sync(0xffffffffu, s, o);
        sq += __shfl_xor_sync(0xffffffffu, sq, o);
    }
    float mean = s * (1.f / D_);
    float rstd = rsqrtf(sq * (1.f / D_) - mean * mean + EPS_);

#pragma unroll
    for (int j = 0; j < 4; ++j) {
        int col = j * 128 + lane * 4;
        float4 gv = *reinterpret_cast<const float4*>(g + col);
        float4 bv = *reinterpret_cast<const float4*>(beta + col);
        float r0 = (v[j][0] - mean) * rstd * gv.x + bv.x;
        float r1 = (v[j][1] - mean) * rstd * gv.y + bv.y;
        float r2 = (v[j][2] - mean) * rstd * gv.z + bv.z;
        float r3 = (v[j][3] - mean) * rstd * gv.w + bv.w;
        *reinterpret_cast<float4*>(out + base + col) = make_float4(r0, r1, r2, r3);
        if (out16) {
            *reinterpret_cast<__half2*>(out16 + base + col)     = __floats2half2_rn(r0, r1);
            *reinterpret_cast<__half2*>(out16 + base + col + 2) = __floats2half2_rn(r2, r3);
        }
    }
}

// ---------------------------------------------------------------------------
// Launch
// ---------------------------------------------------------------------------
extern "C" void kernel_launch(void* const* d_in, const int* in_sizes, int n_in,
                              void* d_out, int out_size)
{
    (void)in_sizes; (void)n_in; (void)out_size;
    const float* tgt        = (const float*)d_in[0];
    const float* memory     = (const float*)d_in[1];
    const float* in_proj_w  = (const float*)d_in[2];
    const float* in_proj_b  = (const float*)d_in[3];
    const float* out_proj_w = (const float*)d_in[4];
    const float* out_proj_b = (const float*)d_in[5];
    const float* sw_q_w = (const float*)d_in[6];
    const float* sw_q_b = (const float*)d_in[7];
    const float* sw_k_w = (const float*)d_in[8];
    const float* sw_k_b = (const float*)d_in[9];
    const float* sw_v_w = (const float*)d_in[10];
    const float* sw_v_b = (const float*)d_in[11];
    const float* sw_o_w = (const float*)d_in[12];
    const float* sw_o_b = (const float*)d_in[13];
    const float* lin1_w = (const float*)d_in[14];
    const float* lin1_b = (const float*)d_in[15];
    const float* lin2_w = (const float*)d_in[16];
    const float* lin2_b = (const float*)d_in[17];
    const float* n1_g = (const float*)d_in[18];
    const float* n1_b = (const float*)d_in[19];
    const float* n2_g = (const float*)d_in[20];
    const float* n2_b = (const float*)d_in[21];
    const float* n3_g = (const float*)d_in[22];
    const float* n3_b = (const float*)d_in[23];
    float* out = (float*)d_out;

    float* s = nullptr;
    cudaGetSymbolAddress((void**)&s, g_scratch);
    float* x1   = s + FOFF_X1;
    float* x2   = s + FOFF_X2;
    float* bcat = s + FOFF_BCAT;
    __half* hb = (__half*)(s + HALF_BASE_F);
    __half* qkv16    = hb + HOFF_QKV;
    __half* attn16   = hb + HOFF_ATTN;
    __half* swq16    = hb + HOFF_SWQ;
    __half* swkv16   = hb + HOFF_SWKV;
    __half* swattn16 = hb + HOFF_SWATTN;
    __half* hbuf16   = hb + HOFF_HBUF;
    __half* tgt16    = hb + HOFF_TGT;
    __half* mem16    = hb + HOFF_MEM;
    __half* x1h      = hb + HOFF_X1H;
    __half* x2h      = hb + HOFF_X2H;
    __half* w_in     = hb + HOFF_WIN;
    __half* w_out    = hb + HOFF_WOUT;
    __half* w_swq    = hb + HOFF_WSWQ;
    __half* w_swkv   = hb + HOFF_WSWKV;
    __half* w_swo    = hb + HOFF_WSWO;
    __half* w_lin1   = hb + HOFF_WLIN1;
    __half* w_lin2   = hb + HOFF_WLIN2;
    __half* proj16   = hb + HOFF_PROJ16;
    __half* ff16     = hb + HOFF_FF16;

    cudaFuncSetAttribute(self_attn_f16_kernel,
                         cudaFuncAttributeMaxDynamicSharedMemorySize, ATTN_SMEM);
    cudaFuncSetAttribute(sw_attn_f16_kernel,
                         cudaFuncAttributeMaxDynamicSharedMemorySize, SWA_SMEM);
    cudaFuncSetAttribute(gemm_f16_kernel,
                         cudaFuncAttributeMaxDynamicSharedMemorySize, G128_SMEM);
    cudaFuncSetAttribute(gemm_f16_dual_kernel,
                         cudaFuncAttributeMaxDynamicSharedMemorySize, G128_SMEM);
    cudaFuncSetAttribute(gemm_f16_n64_kernel,
                         cudaFuncAttributeMaxDynamicSharedMemorySize, G64_SMEM);

    // one fused convert (incl. KV weight concat + bias concat)
    f2h_multi_kernel<<<8192, 256>>>(tgt, tgt16, memory, mem16,
                                    in_proj_w, w_in, out_proj_w, w_out,
                                    sw_q_w, w_swq, sw_o_w, w_swo,
                                    lin1_w, w_lin1, lin2_w, w_lin2,
                                    sw_k_w, w_swkv, sw_v_w, w_swkv + 262144,
                                    sw_k_b, sw_v_b, bcat);

    // combined QKV (N=1536, 12 blocks) + fused KV (N=1024, 8 blocks)
    gemm_f16_dual_kernel<<<dim3(20, 32), 256, G128_SMEM>>>(
        tgt16, w_in, in_proj_b, qkv16, 3 * D_,
        mem16, w_swkv, bcat, swkv16, 1024,
        D_, 12);
    // self attention
    self_attn_f16_kernel<<<dim3(8, 32), 256, ATTN_SMEM>>>(qkv16, attn16);
    // out projection -> fp16
    gemm_f16_n64_kernel<<<dim3(8, 32), 128, G64_SMEM>>>(attn16, w_out, out_proj_b, proj16,
                                                        NROWS, D_, D_, 0, 1);
    // add + LN1 (warp-per-row)
    add_ln_h_kernel<<<NROWS / 8, 256>>>(tgt, proj16, n1_g, n1_b, x1, x1h);
    // sw q projection
    gemm_f16_n64_kernel<<<dim3(8, 32), 128, G64_SMEM>>>(x1h, w_swq, sw_q_b, swq16,
                                                        NROWS, D_, D_, 0, 1);
    // banded attention
    sw_attn_f16_kernel<<<dim3(8, 32), 256, SWA_SMEM>>>(swq16, swkv16, swattn16);
    // sw out projection -> fp16
    gemm_f16_n64_kernel<<<dim3(8, 32), 128, G64_SMEM>>>(swattn16, w_swo, sw_o_b, proj16,
                                                        NROWS, D_, D_, 0, 1);
    // add + LN2
    add_ln_h_kernel<<<NROWS / 8, 256>>>(x1, proj16, n2_g, n2_b, x2, x2h);
    // FFN up + ReLU
    gemm_f16_kernel<<<dim3(16, 32), 256, G128_SMEM>>>(x2h, w_lin1, lin1_b, hbuf16,
                                                      NROWS, DFF_, D_, 1, 1);
    // FFN down -> fp16
    gemm_f16_n64_kernel<<<dim3(8, 32), 128, G64_SMEM>>>(hbuf16, w_lin2, lin2_b, ff16,
                                                        NROWS, D_, DFF_, 0, 1);
    // add + LN3 -> output (fp32 only)
    add_ln_h_kernel<<<NROWS / 8, 256>>>(x2, ff16, n3_g, n3_b, out, nullptr);
}